// round 12
// baseline (speedup 1.0000x reference)
#include <cuda_runtime.h>

#define Bb 32
#define Nn 1024
#define Hh 128
#define THREADS 256
#define WARPS 8
#define RPT 4
#define NPAIR 2
#define ROWS_PER_BLOCK (WARPS * RPT)  // 32
#define GRIDX (Nn / ROWS_PER_BLOCK)   // 32
#define KNOD 128
#define NB_TBL 8

__device__ int   g_cnt[Bb];    // per-batch tickets (reset after use)

// precomputed, pharma-first reordered per batch
__device__ float2 g_AC[Bb * Nn];
__device__ float4 g_P[Bb * Nn];
__device__ float4 g_Q[Bb * Nn];
__device__ float  g_nn[Bb * Nn];
__device__ int    g_oidx[Bb * Nn];
__device__ int    g_npj[Bb];

// per-batch interpolation tables over nu = norm_i
__device__ float4 g_tblPh[Bb * KNOD];  // sum over j <  njc32 (cheap-form)
__device__ float4 g_tblCh[Bb * KNOD];  // sum over j >= njc32 (cheap-form)

// norm range via idempotent int-bit atomics (norms >= 0 so int order == float order)
#define INF8 0x7f7fffff,0x7f7fffff,0x7f7fffff,0x7f7fffff,0x7f7fffff,0x7f7fffff,0x7f7fffff,0x7f7fffff
__device__ int g_rmin[Bb] = {INF8, INF8, INF8, INF8};
__device__ int g_rmax[Bb];  // zero-init; norms >= 0

typedef unsigned long long u64c;

__device__ __forceinline__ float ex2f_(float x) {
    float y; asm("ex2.approx.ftz.f32 %0, %1;" : "=f"(y) : "f"(x)); return y;
}
__device__ __forceinline__ float sqrtf_(float x) {
    float y; asm("sqrt.approx.ftz.f32 %0, %1;" : "=f"(y) : "f"(x)); return y;
}
__device__ __forceinline__ bool mask_at(const void* m, int idx, int isByte) {
    if (isByte) return ((const unsigned char*)m)[idx] != 0;
    return ((const int*)m)[idx] != 0;
}

__device__ __forceinline__ u64c pk2(float lo, float hi) {
    u64c r; asm("mov.b64 %0, {%1, %2};" : "=l"(r) : "f"(lo), "f"(hi)); return r;
}
__device__ __forceinline__ void upk2(float& lo, float& hi, u64c v) {
    asm("mov.b64 {%0, %1}, %2;" : "=f"(lo), "=f"(hi) : "l"(v));
}
__device__ __forceinline__ u64c fma2_(u64c a, u64c b, u64c c) {
    u64c r; asm("fma.rn.f32x2 %0, %1, %2, %3;" : "=l"(r) : "l"(a), "l"(b), "l"(c)); return r;
}
__device__ __forceinline__ u64c add2_(u64c a, u64c b) {
    u64c r; asm("add.rn.f32x2 %0, %1, %2;" : "=l"(r) : "l"(a), "l"(b)); return r;
}
__device__ __forceinline__ u64c mul2_(u64c a, u64c b) {
    u64c r; asm("mul.rn.f32x2 %0, %1, %2;" : "=l"(r) : "l"(a), "l"(b)); return r;
}

__device__ __forceinline__ float pair_term(float2 AC, float4 P, float cbw,
                                           float pxi, float pyi, float pzi,
                                           float sqi, float nrm) {
    float t = fmaf(P.z, pzi, P.w);
    t = fmaf(P.y, pyi, t);
    t = fmaf(P.x, pxi, t);
    float d2 = fmaxf(sqi + t, 1e-12f);
    float dist = sqrtf_(d2);
    float s = fmaf(nrm, AC.x, AC.y);
    s = fmaf(cbw, dist, s);
    return ex2f_(s);
}

__device__ __forceinline__ float4 interp4(const float4* __restrict__ tbl,
                                          float nu, float vmin, float invh) {
    float t = (nu - vmin) * invh;
    t = fminf(fmaxf(t, 0.f), (float)(KNOD - 1));
    int k = (int)t;
    if (k > KNOD - 2) k = KNOD - 2;
    float f = t - (float)k;
    float4 a = tbl[k], b4 = tbl[k + 1];
    return make_float4(fmaf(f, b4.x - a.x, a.x),
                       fmaf(f, b4.y - a.y, a.y),
                       fmaf(f, b4.z - a.z, a.z),
                       fmaf(f, b4.w - a.w, a.w));
}

// ---------------------------------------------------------------------------
// Precompute (grid (4,Bb)): mask-dtype detect, 9-scalar collapse, pharma-first
// reorder + SoA + gated MLP + norm-range atomics.
// ---------------------------------------------------------------------------
__global__ __launch_bounds__(THREADS)
void pre_kernel(const float* __restrict__ pos,
                const void* __restrict__ node_mask,
                const float* __restrict__ p,
                const void* __restrict__ pharma,
                const float* __restrict__ lin1_w,
                const float* __restrict__ lin1_b,
                const float* __restrict__ lin2_w,
                const float* __restrict__ lin2_b,
                const float* __restrict__ wp,
                const float* __restrict__ bp,
                const float* __restrict__ wd,
                const float* __restrict__ wc) {
    __shared__ int   s_chk[32];
    __shared__ int   s_npj;
    __shared__ float s_l1w[Hh], s_l1b[Hh], s_l2w[Hh];
    __shared__ float s_prm[9];

    const int b = blockIdx.y;
    const int q = blockIdx.x;
    const int tid = threadIdx.x;
    const int w = tid >> 5;
    const int lane = tid & 31;

    if (tid < Hh) {
        s_l1w[tid] = lin1_w[tid];
        s_l1b[tid] = lin1_b[tid];
        s_l2w[tid] = lin2_w[tid];
    }

    int any = (tid < 256) && (((const unsigned int*)node_mask)[tid] > 1u);
    const int isB = __syncthreads_or(any) ? 1 : 0;

    if (w == 0) {
        const float L2E = 1.4426950408889634f;
        float u0 = 0.f, u1 = 0.f, u2 = 0.f, au = 0.f;
        float v0 = 0.f, v1 = 0.f, v2 = 0.f, av = 0.f, kd = 0.f;
        for (int h = lane; h < Hh; h += 32) {
            float w1h = wc[h];
            float w2h = wc[Hh + h];
            float a = lin1_w[h] * w1h;
            float c = lin1_b[h] * w1h;
            float wp0 = wp[h * 3 + 0], wp1 = wp[h * 3 + 1], wp2 = wp[h * 3 + 2];
            u0 = fmaf(a, wp0, u0); u1 = fmaf(a, wp1, u1); u2 = fmaf(a, wp2, u2);
            au = fmaf(a, bp[h], au);
            v0 = fmaf(c, wp0, v0); v1 = fmaf(c, wp1, v1); v2 = fmaf(c, wp2, v2);
            av = fmaf(c, bp[h], av);
            kd = fmaf(wd[h], w2h, kd);
        }
        #pragma unroll
        for (int o = 16; o > 0; o >>= 1) {
            u0 += __shfl_xor_sync(0xFFFFFFFFu, u0, o);
            u1 += __shfl_xor_sync(0xFFFFFFFFu, u1, o);
            u2 += __shfl_xor_sync(0xFFFFFFFFu, u2, o);
            au += __shfl_xor_sync(0xFFFFFFFFu, au, o);
            v0 += __shfl_xor_sync(0xFFFFFFFFu, v0, o);
            v1 += __shfl_xor_sync(0xFFFFFFFFu, v1, o);
            v2 += __shfl_xor_sync(0xFFFFFFFFu, v2, o);
            av += __shfl_xor_sync(0xFFFFFFFFu, av, o);
            kd += __shfl_xor_sync(0xFFFFFFFFu, kd, o);
        }
        if (lane == 0) {
            s_prm[0] = u0 * L2E; s_prm[1] = u1 * L2E; s_prm[2] = u2 * L2E; s_prm[3] = au * L2E;
            s_prm[4] = v0 * L2E; s_prm[5] = v1 * L2E; s_prm[6] = v2 * L2E; s_prm[7] = av * L2E;
            s_prm[8] = kd * L2E;
        }
    }

    #pragma unroll
    for (int k = 0; k < Nn / THREADS; k++) {
        int j = k * THREADS + tid;
        bool ph = mask_at(pharma, b * Nn + j, isB);
        unsigned m = __ballot_sync(0xFFFFFFFFu, ph);
        if (lane == 0) s_chk[k * WARPS + w] = __popc(m);
    }
    __syncthreads();
    if (tid < 32) {
        int v = s_chk[tid];
        int incl = v;
        #pragma unroll
        for (int o = 1; o < 32; o <<= 1) {
            int t = __shfl_up_sync(0xFFFFFFFFu, incl, o);
            if (lane >= o) incl += t;
        }
        s_chk[tid] = incl - v;
        if (tid == 31) s_npj = incl;
    }
    __syncthreads();
    const int npj = s_npj;

    const float u0 = s_prm[0], u1 = s_prm[1], u2 = s_prm[2], au = s_prm[3];
    const float v0 = s_prm[4], v1 = s_prm[5], v2 = s_prm[6], av = s_prm[7];
    const float kdL = s_prm[8];
    const float l2b = lin2_b[0];

    {
        int j = q * THREADS + tid;
        bool ph = mask_at(pharma, b * Nn + j, isB);
        unsigned m = __ballot_sync(0xFFFFFFFFu, ph);
        unsigned below = m & ((1u << lane) - 1u);
        int c = q * WARPS + w;
        int phOff = s_chk[c];
        int pos_;
        if (ph) pos_ = phOff + __popc(below);
        else    pos_ = npj + (c * 32 - phOff) + (lane - __popc(below));

        const float* posb = pos + (size_t)b * Nn * 3;
        const float* pb   = p   + (size_t)b * Nn * 3;
        float qx = posb[j * 3 + 0], qy = posb[j * 3 + 1], qz = posb[j * 3 + 2];
        float A = fmaf(qx, u0, fmaf(qy, u1, fmaf(qz, u2, au)));
        float C = fmaf(qx, v0, fmaf(qy, v1, fmaf(qz, v2, av)));
        float px = pb[j * 3 + 0], py = pb[j * 3 + 1], pz = pb[j * 3 + 2];
        float sq = fmaf(px, px, fmaf(py, py, pz * pz));

        int gp = b * Nn + pos_;
        g_AC[gp] = make_float2(A, C);
        g_P[gp]  = make_float4(-2.f * px, -2.f * py, -2.f * pz, sq);
        g_Q[gp]  = make_float4(qx, qy, qz, ph ? kdL : 0.f);
        g_oidx[gp] = j;

        float nrm = sqrtf(fmaf(qx, qx, fmaf(qy, qy, qz * qz)));

        // norm-range: warp-reduce then lane0 idempotent atomics
        float mn = nrm, mx = nrm;
        #pragma unroll
        for (int o = 16; o > 0; o >>= 1) {
            mn = fminf(mn, __shfl_xor_sync(0xFFFFFFFFu, mn, o));
            mx = fmaxf(mx, __shfl_xor_sync(0xFFFFFFFFu, mx, o));
        }
        if (lane == 0) {
            atomicMin(&g_rmin[b], __float_as_int(mn));
            atomicMax(&g_rmax[b], __float_as_int(mx));
        }

        // per-row MLP (R10 form), gated by node_mask
        float nn = 0.f;
        #pragma unroll 8
        for (int h = 0; h < Hh; h++) {
            float hid = fmaf(nrm, s_l1w[h], s_l1b[h]);
            nn = fmaf(fmaxf(hid, 0.f), s_l2w[h], nn);
        }
        bool node = mask_at(node_mask, b * Nn + j, isB);
        g_nn[gp] = node ? (nn + l2b) : 0.f;
    }

    if (q == 0 && tid == 0) g_npj[b] = npj;
}

// ---------------------------------------------------------------------------
// Table build (grid (8,Bb)): 2 nodes per warp, direct L2 reads, no smem stage.
// ---------------------------------------------------------------------------
__global__ __launch_bounds__(THREADS)
void tbl_kernel() {
    const int b = blockIdx.y;
    const int xb = blockIdx.x;
    const int tid = threadIdx.x;
    const int w = tid >> 5;
    const int lane = tid & 31;

    const float vmin = __int_as_float(g_rmin[b]);
    const float vmax = __int_as_float(g_rmax[b]);
    const float h = (vmax - vmin) * (1.f / (KNOD - 1));
    const int npj = g_npj[b];
    const int njc = (npj + 31) >> 5;

    const float2* __restrict__ AC = &g_AC[b * Nn];
    const float4* __restrict__ Q  = &g_Q[b * Nn];

    const int k0 = (xb * WARPS + w) * 2;
    const float nu0 = fmaf((float)k0, h, vmin);
    const float nu1 = fmaf((float)(k0 + 1), h, vmin);

    float S0p = 0.f, x0p = 0.f, y0p = 0.f, z0p = 0.f;
    float S1p = 0.f, x1p = 0.f, y1p = 0.f, z1p = 0.f;
    float S0c = 0.f, x0c = 0.f, y0c = 0.f, z0c = 0.f;
    float S1c = 0.f, x1c = 0.f, y1c = 0.f, z1c = 0.f;

    int it = 0;
    #pragma unroll 4
    for (; it < njc; it++) {
        int j = it * 32 + lane;
        float2 ac = __ldg(&AC[j]); float4 q = __ldg(&Q[j]);
        float e0 = ex2f_(fmaf(nu0, ac.x, ac.y));
        float e1 = ex2f_(fmaf(nu1, ac.x, ac.y));
        S0p += e0; x0p = fmaf(e0, q.x, x0p); y0p = fmaf(e0, q.y, y0p); z0p = fmaf(e0, q.z, z0p);
        S1p += e1; x1p = fmaf(e1, q.x, x1p); y1p = fmaf(e1, q.y, y1p); z1p = fmaf(e1, q.z, z1p);
    }
    #pragma unroll 4
    for (; it < Nn / 32; it++) {
        int j = it * 32 + lane;
        float2 ac = __ldg(&AC[j]); float4 q = __ldg(&Q[j]);
        float e0 = ex2f_(fmaf(nu0, ac.x, ac.y));
        float e1 = ex2f_(fmaf(nu1, ac.x, ac.y));
        S0c += e0; x0c = fmaf(e0, q.x, x0c); y0c = fmaf(e0, q.y, y0c); z0c = fmaf(e0, q.z, z0c);
        S1c += e1; x1c = fmaf(e1, q.x, x1c); y1c = fmaf(e1, q.y, y1c); z1c = fmaf(e1, q.z, z1c);
    }
    #pragma unroll
    for (int o = 16; o > 0; o >>= 1) {
        S0p += __shfl_xor_sync(0xFFFFFFFFu, S0p, o);
        x0p += __shfl_xor_sync(0xFFFFFFFFu, x0p, o);
        y0p += __shfl_xor_sync(0xFFFFFFFFu, y0p, o);
        z0p += __shfl_xor_sync(0xFFFFFFFFu, z0p, o);
        S1p += __shfl_xor_sync(0xFFFFFFFFu, S1p, o);
        x1p += __shfl_xor_sync(0xFFFFFFFFu, x1p, o);
        y1p += __shfl_xor_sync(0xFFFFFFFFu, y1p, o);
        z1p += __shfl_xor_sync(0xFFFFFFFFu, z1p, o);
        S0c += __shfl_xor_sync(0xFFFFFFFFu, S0c, o);
        x0c += __shfl_xor_sync(0xFFFFFFFFu, x0c, o);
        y0c += __shfl_xor_sync(0xFFFFFFFFu, y0c, o);
        z0c += __shfl_xor_sync(0xFFFFFFFFu, z0c, o);
        S1c += __shfl_xor_sync(0xFFFFFFFFu, S1c, o);
        x1c += __shfl_xor_sync(0xFFFFFFFFu, x1c, o);
        y1c += __shfl_xor_sync(0xFFFFFFFFu, y1c, o);
        z1c += __shfl_xor_sync(0xFFFFFFFFu, z1c, o);
    }
    if (lane == 0) {
        g_tblPh[b * KNOD + k0]     = make_float4(S0p, x0p, y0p, z0p);
        g_tblPh[b * KNOD + k0 + 1] = make_float4(S1p, x1p, y1p, z1p);
        g_tblCh[b * KNOD + k0]     = make_float4(S0c, x0c, y0c, z0c);
        g_tblCh[b * KNOD + k0 + 1] = make_float4(S1c, x1c, y1c, z1c);
    }
}

// ---------------------------------------------------------------------------
// Main kernel: pharma rows = exact dist loop over j<njc32 + cheap table;
// cheap rows = pure table lookups. Preamble trimmed to jcap entries.
// ---------------------------------------------------------------------------
__global__ __launch_bounds__(THREADS, 3)
void attn_kernel(float* __restrict__ out) {
    __shared__ float2 s_AC[Nn];
    __shared__ float4 s_P[Nn];
    __shared__ float4 s_Q[Nn];
    __shared__ float  s_red[WARPS];
    __shared__ float  s_mean[3];
    __shared__ int    s_tk;

    const int b = blockIdx.y;
    const int tid = threadIdx.x;
    const int w = tid >> 5;
    const int lane = tid & 31;

    const int npj = g_npj[b];
    const int njc = (npj + 31) >> 5;
    const int jcap = min(Nn, (njc + 1) * 32);
    const int rb = blockIdx.x * ROWS_PER_BLOCK;

    if (rb < npj) {   // block-uniform
        const float4* gp = (const float4*)&g_P[b * Nn];
        const float4* gq = (const float4*)&g_Q[b * Nn];
        const float4* ga = (const float4*)&g_AC[b * Nn];
        float4* sp = (float4*)s_P;
        float4* sq = (float4*)s_Q;
        float4* sa = (float4*)s_AC;
        for (int i = tid; i < jcap; i += THREADS) { sp[i] = gp[i]; sq[i] = gq[i]; }
        for (int i = tid; i < jcap / 2; i += THREADS) sa[i] = ga[i];
        __syncthreads();
    }

    const int p0 = rb + w * RPT;
    const float vmin = __int_as_float(g_rmin[b]);
    const float vmax = __int_as_float(g_rmax[b]);
    const float invh = (vmax > vmin) ? (float)(KNOD - 1) / (vmax - vmin) : 0.f;

    if (p0 < npj) {
        // ---- loop path ----
        const int cls0 = (p0 + RPT <= npj);

        u64c px2[NPAIR], py2[NPAIR], pz2[NPAIR], sq2[NPAIR], nrm2[NPAIR], rg2[NPAIR];
        u64c sum2[NPAIR], cx2[NPAIR], cy2[NPAIR], cz2[NPAIR];
        #pragma unroll
        for (int t = 0; t < NPAIR; t++) {
            int pa = p0 + 2 * t, pb_ = pa + 1;
            float4 Pa = s_P[pa], Pb = s_P[pb_];
            px2[t] = pk2(-0.5f * Pa.x, -0.5f * Pb.x);
            py2[t] = pk2(-0.5f * Pa.y, -0.5f * Pb.y);
            pz2[t] = pk2(-0.5f * Pa.z, -0.5f * Pb.z);
            sq2[t] = pk2(Pa.w, Pb.w);
            float4 Qa = s_Q[pa], Qb = s_Q[pb_];
            float na = sqrtf(fmaf(Qa.x, Qa.x, fmaf(Qa.y, Qa.y, Qa.z * Qa.z)));
            float nb = sqrtf(fmaf(Qb.x, Qb.x, fmaf(Qb.y, Qb.y, Qb.z * Qb.z)));
            nrm2[t] = pk2(na, nb);
            rg2[t] = pk2((pa < npj) ? 1.f : 0.f, (pb_ < npj) ? 1.f : 0.f);
            sum2[t] = 0ull; cx2[t] = 0ull; cy2[t] = 0ull; cz2[t] = 0ull;
        }

        if (cls0) {
            #pragma unroll 2
            for (int jj = 0; jj < njc; jj++) {
                const int j = jj * 32 + lane;
                const float2 AC = s_AC[j];
                const float4 P  = s_P[j];
                const float4 Q  = s_Q[j];
                u64c A2 = pk2(AC.x, AC.x), C2 = pk2(AC.y, AC.y);
                u64c Px2 = pk2(P.x, P.x), Py2 = pk2(P.y, P.y);
                u64c Pz2 = pk2(P.z, P.z), Pw2 = pk2(P.w, P.w);
                u64c Qx2 = pk2(Q.x, Q.x), Qy2 = pk2(Q.y, Q.y), Qz2 = pk2(Q.z, Q.z);
                u64c cb2 = pk2(Q.w, Q.w);
                #pragma unroll
                for (int t = 0; t < NPAIR; t++) {
                    u64c tt = fma2_(Pz2, pz2[t], Pw2);
                    tt = fma2_(Py2, py2[t], tt);
                    tt = fma2_(Px2, px2[t], tt);
                    u64c d2 = add2_(sq2[t], tt);
                    float da, db; upk2(da, db, d2);
                    float ra = sqrtf_(fmaxf(da, 1e-12f));
                    float rb_ = sqrtf_(fmaxf(db, 1e-12f));
                    u64c s2 = fma2_(nrm2[t], A2, C2);
                    s2 = fma2_(cb2, pk2(ra, rb_), s2);
                    float sa, sb; upk2(sa, sb, s2);
                    u64c e2 = pk2(ex2f_(sa), ex2f_(sb));
                    sum2[t] = add2_(sum2[t], e2);
                    cx2[t] = fma2_(e2, Qx2, cx2[t]);
                    cy2[t] = fma2_(e2, Qy2, cy2[t]);
                    cz2[t] = fma2_(e2, Qz2, cz2[t]);
                }
            }
        } else {
            #pragma unroll 2
            for (int jj = 0; jj < njc; jj++) {
                const int j = jj * 32 + lane;
                const float2 AC = s_AC[j];
                const float4 P  = s_P[j];
                const float4 Q  = s_Q[j];
                u64c A2 = pk2(AC.x, AC.x), C2 = pk2(AC.y, AC.y);
                u64c Px2 = pk2(P.x, P.x), Py2 = pk2(P.y, P.y);
                u64c Pz2 = pk2(P.z, P.z), Pw2 = pk2(P.w, P.w);
                u64c Qx2 = pk2(Q.x, Q.x), Qy2 = pk2(Q.y, Q.y), Qz2 = pk2(Q.z, Q.z);
                u64c cb2 = pk2(Q.w, Q.w);
                #pragma unroll
                for (int t = 0; t < NPAIR; t++) {
                    u64c tt = fma2_(Pz2, pz2[t], Pw2);
                    tt = fma2_(Py2, py2[t], tt);
                    tt = fma2_(Px2, px2[t], tt);
                    u64c d2 = add2_(sq2[t], tt);
                    float da, db; upk2(da, db, d2);
                    float ra = sqrtf_(fmaxf(da, 1e-12f));
                    float rb_ = sqrtf_(fmaxf(db, 1e-12f));
                    u64c cbt = mul2_(cb2, rg2[t]);
                    u64c s2 = fma2_(nrm2[t], A2, C2);
                    s2 = fma2_(cbt, pk2(ra, rb_), s2);
                    float sa, sb; upk2(sa, sb, s2);
                    u64c e2 = pk2(ex2f_(sa), ex2f_(sb));
                    sum2[t] = add2_(sum2[t], e2);
                    cx2[t] = fma2_(e2, Qx2, cx2[t]);
                    cy2[t] = fma2_(e2, Qy2, cy2[t]);
                    cz2[t] = fma2_(e2, Qz2, cz2[t]);
                }
            }
        }

        float sum[RPT], cx[RPT], cy[RPT], cz[RPT];
        #pragma unroll
        for (int t = 0; t < NPAIR; t++) {
            upk2(sum[2 * t], sum[2 * t + 1], sum2[t]);
            upk2(cx[2 * t],  cx[2 * t + 1],  cx2[t]);
            upk2(cy[2 * t],  cy[2 * t + 1],  cy2[t]);
            upk2(cz[2 * t],  cz[2 * t + 1],  cz2[t]);
        }
        #pragma unroll
        for (int r = 0; r < RPT; r++) {
            #pragma unroll
            for (int o = 16; o > 0; o >>= 1) {
                sum[r] += __shfl_xor_sync(0xFFFFFFFFu, sum[r], o);
                cx[r]  += __shfl_xor_sync(0xFFFFFFFFu, cx[r], o);
                cy[r]  += __shfl_xor_sync(0xFFFFFFFFu, cy[r], o);
                cz[r]  += __shfl_xor_sync(0xFFFFFFFFu, cz[r], o);
            }
        }

        #pragma unroll
        for (int r = 0; r < RPT; r++) {
            if (lane == r) {
                int pi = p0 + r;
                float4 Q = s_Q[pi];
                float4 P = s_P[pi];
                float nrm = sqrtf(fmaf(Q.x, Q.x, fmaf(Q.y, Q.y, Q.z * Q.z)));
                float S = sum[r], X = cx[r], Y = cy[r], Z = cz[r];
                float rgf = (pi < npj) ? 1.f : 0.f;
                float cbw = Q.w * rgf;
                float pxi = -0.5f * P.x, pyi = -0.5f * P.y, pzi = -0.5f * P.z;
                float e_wrong = pair_term(s_AC[pi], P, cbw, pxi, pyi, pzi, P.w, nrm);
                float e_right = ex2f_(fmaf(nrm, s_AC[pi].x, s_AC[pi].y));
                float d = e_right - e_wrong;
                S += d; X = fmaf(d, Q.x, X); Y = fmaf(d, Q.y, Y); Z = fmaf(d, Q.z, Z);
                float4 tc = interp4(&g_tblCh[b * KNOD], nrm, vmin, invh);
                S += tc.x; X += tc.y; Y += tc.z; Z += tc.w;

                int oi = g_oidx[b * Nn + pi];
                int gi = b * Nn + oi;
                float nn = g_nn[b * Nn + pi];
                float f = nn / (S * (nrm + 1e-5f));
                out[gi * 3 + 0] = Q.x * X * f;
                out[gi * 3 + 1] = Q.y * Y * f;
                out[gi * 3 + 2] = Q.z * Z * f;
            }
        }
    } else {
        // ---- pure table path ----
        if (lane < RPT) {
            int pi = p0 + lane;
            float4 Q = g_Q[b * Nn + pi];
            float nrm = sqrtf(fmaf(Q.x, Q.x, fmaf(Q.y, Q.y, Q.z * Q.z)));
            float4 tp = interp4(&g_tblPh[b * KNOD], nrm, vmin, invh);
            float4 tc = interp4(&g_tblCh[b * KNOD], nrm, vmin, invh);
            float S = tp.x + tc.x, X = tp.y + tc.y, Y = tp.z + tc.z, Z = tp.w + tc.w;
            int oi = g_oidx[b * Nn + pi];
            int gi = b * Nn + oi;
            float nn = g_nn[b * Nn + pi];
            float f = nn / (S * (nrm + 1e-5f));
            out[gi * 3 + 0] = Q.x * X * f;
            out[gi * 3 + 1] = Q.y * Y * f;
            out[gi * 3 + 2] = Q.z * Z * f;
        }
    }

    // fused per-batch mean subtraction (last block of batch)
    __threadfence();
    __syncthreads();
    if (tid == 0) s_tk = atomicAdd(&g_cnt[b], 1);
    __syncthreads();
    if (s_tk == GRIDX - 1) {
        __threadfence();
        float ax = 0.f, ay = 0.f, az = 0.f;
        for (int n = tid; n < Nn; n += THREADS) {
            const float* o = out + ((size_t)b * Nn + n) * 3;
            ax += o[0]; ay += o[1]; az += o[2];
        }
        float* comps[3] = {&ax, &ay, &az};
        #pragma unroll
        for (int c = 0; c < 3; c++) {
            float v = *comps[c];
            #pragma unroll
            for (int o = 16; o > 0; o >>= 1) v += __shfl_xor_sync(0xFFFFFFFFu, v, o);
            if (lane == 0) s_red[w] = v;
            __syncthreads();
            if (tid == 0) {
                float t = 0.f;
                #pragma unroll
                for (int k = 0; k < WARPS; k++) t += s_red[k];
                s_mean[c] = t * (1.f / Nn);
            }
            __syncthreads();
        }
        float mx = s_mean[0], my = s_mean[1], mz = s_mean[2];
        for (int n = tid; n < Nn; n += THREADS) {
            float* o = out + ((size_t)b * Nn + n) * 3;
            o[0] -= mx; o[1] -= my; o[2] -= mz;
        }
        if (tid == 0) atomicExch(&g_cnt[b], 0);
    }
}

extern "C" void kernel_launch(void* const* d_in, const int* in_sizes, int n_in,
                              void* d_out, int out_size) {
    const float* pos       = (const float*)d_in[0];
    const void*  node_mask = d_in[1];
    const float* p         = (const float*)d_in[2];
    const void*  pharma    = d_in[3];
    const float* lin1_w    = (const float*)d_in[4];
    const float* lin1_b    = (const float*)d_in[5];
    const float* lin2_w    = (const float*)d_in[6];
    const float* lin2_b    = (const float*)d_in[7];
    const float* wp        = (const float*)d_in[8];
    const float* bp        = (const float*)d_in[9];
    const float* wd        = (const float*)d_in[10];
    const float* wc        = (const float*)d_in[12];

    dim3 pgrid(Nn / THREADS, Bb);   // (4, 32)
    pre_kernel<<<pgrid, THREADS>>>(pos, node_mask, p, pharma,
                                   lin1_w, lin1_b, lin2_w, lin2_b,
                                   wp, bp, wd, wc);

    dim3 tgrid(NB_TBL, Bb);         // (8, 32)
    tbl_kernel<<<tgrid, THREADS>>>();

    dim3 grid(GRIDX, Bb);
    attn_kernel<<<grid, THREADS>>>((float*)d_out);
}

// round 13
// speedup vs baseline: 1.0290x; 1.0290x over previous
#include <cuda_runtime.h>

#define Bb 32
#define Nn 1024
#define Hh 128
#define THREADS 256
#define WARPS 8
#define RPT 4
#define NPAIR 2
#define ROWS_PER_BLOCK (WARPS * RPT)  // 32
#define GRIDX (Nn / ROWS_PER_BLOCK)   // 32
#define KNOD 128
#define PREB 4                         // prep blocks per batch (nodes split 32/block)

__device__ int   g_cnt[Bb];    // per-batch tickets (reset after use)

// precomputed, pharma-first reordered per batch
__device__ float2 g_AC[Bb * Nn];
__device__ float4 g_P[Bb * Nn];
__device__ float4 g_Q[Bb * Nn];
__device__ float  g_nn[Bb * Nn];
__device__ int    g_oidx[Bb * Nn];
__device__ int    g_npj[Bb];

// per-batch interpolation tables over nu = norm_i
__device__ float4 g_tblPh[Bb * KNOD];  // sum over j <  njc32 (cheap-form)
__device__ float4 g_tblCh[Bb * KNOD];  // sum over j >= njc32 (cheap-form)
__device__ float2 g_range[Bb];         // (vmin, vmax)

typedef unsigned long long u64c;

__device__ __forceinline__ float ex2f_(float x) {
    float y; asm("ex2.approx.ftz.f32 %0, %1;" : "=f"(y) : "f"(x)); return y;
}
__device__ __forceinline__ float sqrtf_(float x) {
    float y; asm("sqrt.approx.ftz.f32 %0, %1;" : "=f"(y) : "f"(x)); return y;
}
__device__ __forceinline__ bool mask_at(const void* m, int idx, int isByte) {
    if (isByte) return ((const unsigned char*)m)[idx] != 0;
    return ((const int*)m)[idx] != 0;
}

__device__ __forceinline__ u64c pk2(float lo, float hi) {
    u64c r; asm("mov.b64 %0, {%1, %2};" : "=l"(r) : "f"(lo), "f"(hi)); return r;
}
__device__ __forceinline__ void upk2(float& lo, float& hi, u64c v) {
    asm("mov.b64 {%0, %1}, %2;" : "=f"(lo), "=f"(hi) : "l"(v));
}
__device__ __forceinline__ u64c fma2_(u64c a, u64c b, u64c c) {
    u64c r; asm("fma.rn.f32x2 %0, %1, %2, %3;" : "=l"(r) : "l"(a), "l"(b), "l"(c)); return r;
}
__device__ __forceinline__ u64c add2_(u64c a, u64c b) {
    u64c r; asm("add.rn.f32x2 %0, %1, %2;" : "=l"(r) : "l"(a), "l"(b)); return r;
}
__device__ __forceinline__ u64c mul2_(u64c a, u64c b) {
    u64c r; asm("mul.rn.f32x2 %0, %1, %2;" : "=l"(r) : "l"(a), "l"(b)); return r;
}

__device__ __forceinline__ float pair_term(float2 AC, float4 P, float cbw,
                                           float pxi, float pyi, float pzi,
                                           float sqi, float nrm) {
    float t = fmaf(P.z, pzi, P.w);
    t = fmaf(P.y, pyi, t);
    t = fmaf(P.x, pxi, t);
    float d2 = fmaxf(sqi + t, 1e-12f);
    float dist = sqrtf_(d2);
    float s = fmaf(nrm, AC.x, AC.y);
    s = fmaf(cbw, dist, s);
    return ex2f_(s);
}

__device__ __forceinline__ float4 interp4(const float4* __restrict__ tbl,
                                          float nu, float vmin, float invh) {
    float t = (nu - vmin) * invh;
    t = fminf(fmaxf(t, 0.f), (float)(KNOD - 1));
    int k = (int)t;
    if (k > KNOD - 2) k = KNOD - 2;
    float f = t - (float)k;
    float4 a = tbl[k], b4 = tbl[k + 1];
    return make_float4(fmaf(f, b4.x - a.x, a.x),
                       fmaf(f, b4.y - a.y, a.y),
                       fmaf(f, b4.z - a.z, a.z),
                       fmaf(f, b4.w - a.w, a.w));
}

// ---------------------------------------------------------------------------
// prep_kernel: grid (PREB, Bb), 1024 threads. Each block handles its WHOLE
// batch (1 j/thread): detect, reorder, SoA, range — and builds 32 of the 128
// table nodes from smem. Block q==0 additionally writes the global SoA + MLP.
// ---------------------------------------------------------------------------
__global__ __launch_bounds__(1024)
void prep_kernel(const float* __restrict__ pos,
                 const void* __restrict__ node_mask,
                 const float* __restrict__ p,
                 const void* __restrict__ pharma,
                 const float* __restrict__ lin1_w,
                 const float* __restrict__ lin1_b,
                 const float* __restrict__ lin2_w,
                 const float* __restrict__ lin2_b,
                 const float* __restrict__ wp,
                 const float* __restrict__ bp,
                 const float* __restrict__ wd,
                 const float* __restrict__ wc) {
    __shared__ float2 sAC[Nn];          // reordered
    __shared__ float4 sQ[Nn];           // reordered
    __shared__ int    s_chk[32];
    __shared__ int    s_npj;
    __shared__ float  s_l1w[Hh], s_l1b[Hh], s_l2w[Hh];
    __shared__ float  sMn[32], sMx[32];
    __shared__ float  s_vmin, s_vmax;

    const int b = blockIdx.y;
    const int q = blockIdx.x;
    const int tid = threadIdx.x;
    const int w = tid >> 5;
    const int lane = tid & 31;
    const int j = tid;                  // one j per thread

    if (tid < Hh) {
        s_l1w[tid] = lin1_w[tid];
        s_l1b[tid] = lin1_b[tid];
        s_l2w[tid] = lin2_w[tid];
    }

    // early input loads (independent of everything below)
    const float* posb = pos + (size_t)b * Nn * 3;
    const float* pb   = p   + (size_t)b * Nn * 3;
    float qx = posb[j * 3 + 0], qy = posb[j * 3 + 1], qz = posb[j * 3 + 2];
    float px = pb[j * 3 + 0],   py = pb[j * 3 + 1],   pz = pb[j * 3 + 2];

    // mask-dtype detection (256 words, P[miss]=8^-256); barrier A
    int any = (tid < 256) && (((const unsigned int*)node_mask)[tid] > 1u);
    const int isB = __syncthreads_or(any) ? 1 : 0;

    bool ph   = mask_at(pharma,    b * Nn + j, isB);
    bool node = mask_at(node_mask, b * Nn + j, isB);
    unsigned m = __ballot_sync(0xFFFFFFFFu, ph);
    if (lane == 0) s_chk[w] = __popc(m);

    // 9-scalar collapse: every warp computes it redundantly in registers
    float u0, u1, u2, au, v0, v1, v2, av, kdL;
    {
        const float L2E = 1.4426950408889634f;
        float a0 = 0.f, a1 = 0.f, a2 = 0.f, a3 = 0.f;
        float c0 = 0.f, c1 = 0.f, c2 = 0.f, c3 = 0.f, k8 = 0.f;
        #pragma unroll
        for (int h = lane; h < Hh; h += 32) {
            float w1h = wc[h];
            float w2h = wc[Hh + h];
            float a = lin1_w[h] * w1h;
            float c = lin1_b[h] * w1h;
            float wp0 = wp[h * 3 + 0], wp1 = wp[h * 3 + 1], wp2 = wp[h * 3 + 2];
            a0 = fmaf(a, wp0, a0); a1 = fmaf(a, wp1, a1); a2 = fmaf(a, wp2, a2);
            a3 = fmaf(a, bp[h], a3);
            c0 = fmaf(c, wp0, c0); c1 = fmaf(c, wp1, c1); c2 = fmaf(c, wp2, c2);
            c3 = fmaf(c, bp[h], c3);
            k8 = fmaf(wd[h], w2h, k8);
        }
        #pragma unroll
        for (int o = 16; o > 0; o >>= 1) {
            a0 += __shfl_xor_sync(0xFFFFFFFFu, a0, o);
            a1 += __shfl_xor_sync(0xFFFFFFFFu, a1, o);
            a2 += __shfl_xor_sync(0xFFFFFFFFu, a2, o);
            a3 += __shfl_xor_sync(0xFFFFFFFFu, a3, o);
            c0 += __shfl_xor_sync(0xFFFFFFFFu, c0, o);
            c1 += __shfl_xor_sync(0xFFFFFFFFu, c1, o);
            c2 += __shfl_xor_sync(0xFFFFFFFFu, c2, o);
            c3 += __shfl_xor_sync(0xFFFFFFFFu, c3, o);
            k8 += __shfl_xor_sync(0xFFFFFFFFu, k8, o);
        }
        u0 = a0 * L2E; u1 = a1 * L2E; u2 = a2 * L2E; au = a3 * L2E;
        v0 = c0 * L2E; v1 = c1 * L2E; v2 = c2 * L2E; av = c3 * L2E;
        kdL = k8 * L2E;
    }

    __syncthreads();                    // barrier B: s_chk ready
    if (tid < 32) {                     // exclusive scan of 32 chunk counts
        int v = s_chk[tid];
        int incl = v;
        #pragma unroll
        for (int o = 1; o < 32; o <<= 1) {
            int t = __shfl_up_sync(0xFFFFFFFFu, incl, o);
            if (lane >= o) incl += t;
        }
        s_chk[tid] = incl - v;
        if (tid == 31) s_npj = incl;
    }
    __syncthreads();                    // barrier C
    const int npj = s_npj;

    // reorder + SoA
    unsigned below = m & ((1u << lane) - 1u);
    int phOff = s_chk[w];
    int pos_;
    if (ph) pos_ = phOff + __popc(below);
    else    pos_ = npj + (w * 32 - phOff) + (lane - __popc(below));

    float A = fmaf(qx, u0, fmaf(qy, u1, fmaf(qz, u2, au)));
    float C = fmaf(qx, v0, fmaf(qy, v1, fmaf(qz, v2, av)));
    float sq = fmaf(px, px, fmaf(py, py, pz * pz));
    float cb = ph ? kdL : 0.f;

    sAC[pos_] = make_float2(A, C);
    sQ[pos_]  = make_float4(qx, qy, qz, cb);

    int gp = b * Nn + pos_;
    if (q == 0) {
        g_AC[gp] = make_float2(A, C);
        g_P[gp]  = make_float4(-2.f * px, -2.f * py, -2.f * pz, sq);
        g_Q[gp]  = make_float4(qx, qy, qz, cb);
        g_oidx[gp] = j;
    }

    float nrm = sqrtf(fmaf(qx, qx, fmaf(qy, qy, qz * qz)));

    // norm range: warp reduce -> block reduce (deterministic fixed order)
    float mn = nrm, mx = nrm;
    #pragma unroll
    for (int o = 16; o > 0; o >>= 1) {
        mn = fminf(mn, __shfl_xor_sync(0xFFFFFFFFu, mn, o));
        mx = fmaxf(mx, __shfl_xor_sync(0xFFFFFFFFu, mx, o));
    }
    if (lane == 0) { sMn[w] = mn; sMx[w] = mx; }
    __syncthreads();                    // barrier D (also covers sAC/sQ writes)
    if (tid == 0) {
        float a = sMn[0], c = sMx[0];
        #pragma unroll
        for (int k = 1; k < 32; k++) { a = fminf(a, sMn[k]); c = fmaxf(c, sMx[k]); }
        s_vmin = a; s_vmax = c;
        if (q == 0) g_range[b] = make_float2(a, c);
        if (q == 0) g_npj[b] = npj;
    }
    __syncthreads();                    // barrier E
    const float vmin = s_vmin;
    const float hstep = (s_vmax - vmin) * (1.f / (KNOD - 1));
    const int njc = (npj + 31) >> 5;

    // table: this block's 32 nodes, 1 node per warp, from smem
    {
        const int k = q * (KNOD / PREB) + w;
        const float nu = fmaf((float)k, hstep, vmin);
        float Sp = 0.f, xp = 0.f, yp = 0.f, zp = 0.f;
        float Sc = 0.f, xc = 0.f, yc = 0.f, zc = 0.f;
        int it = 0;
        #pragma unroll 4
        for (; it < njc; it++) {
            int jj = it * 32 + lane;
            float2 ac = sAC[jj]; float4 qv = sQ[jj];
            float e = ex2f_(fmaf(nu, ac.x, ac.y));
            Sp += e; xp = fmaf(e, qv.x, xp); yp = fmaf(e, qv.y, yp); zp = fmaf(e, qv.z, zp);
        }
        #pragma unroll 4
        for (; it < Nn / 32; it++) {
            int jj = it * 32 + lane;
            float2 ac = sAC[jj]; float4 qv = sQ[jj];
            float e = ex2f_(fmaf(nu, ac.x, ac.y));
            Sc += e; xc = fmaf(e, qv.x, xc); yc = fmaf(e, qv.y, yc); zc = fmaf(e, qv.z, zc);
        }
        #pragma unroll
        for (int o = 16; o > 0; o >>= 1) {
            Sp += __shfl_xor_sync(0xFFFFFFFFu, Sp, o);
            xp += __shfl_xor_sync(0xFFFFFFFFu, xp, o);
            yp += __shfl_xor_sync(0xFFFFFFFFu, yp, o);
            zp += __shfl_xor_sync(0xFFFFFFFFu, zp, o);
            Sc += __shfl_xor_sync(0xFFFFFFFFu, Sc, o);
            xc += __shfl_xor_sync(0xFFFFFFFFu, xc, o);
            yc += __shfl_xor_sync(0xFFFFFFFFu, yc, o);
            zc += __shfl_xor_sync(0xFFFFFFFFu, zc, o);
        }
        if (lane == 0) {
            g_tblPh[b * KNOD + k] = make_float4(Sp, xp, yp, zp);
            g_tblCh[b * KNOD + k] = make_float4(Sc, xc, yc, zc);
        }
    }

    // per-row MLP (q==0 only), gated by node_mask
    if (q == 0) {
        float nn = 0.f;
        #pragma unroll 8
        for (int h = 0; h < Hh; h++) {
            float hid = fmaf(nrm, s_l1w[h], s_l1b[h]);
            nn = fmaf(fmaxf(hid, 0.f), s_l2w[h], nn);
        }
        g_nn[gp] = node ? (nn + lin2_b[0]) : 0.f;
    }
}

// ---------------------------------------------------------------------------
// Main kernel: pharma rows = exact dist loop over j<njc32 + cheap table;
// cheap rows = pure table lookups.
// ---------------------------------------------------------------------------
__global__ __launch_bounds__(THREADS, 3)
void attn_kernel(float* __restrict__ out) {
    __shared__ float2 s_AC[Nn];
    __shared__ float4 s_P[Nn];
    __shared__ float4 s_Q[Nn];
    __shared__ float  s_red[WARPS];
    __shared__ float  s_mean[3];
    __shared__ int    s_tk;

    const int b = blockIdx.y;
    const int tid = threadIdx.x;
    const int w = tid >> 5;
    const int lane = tid & 31;

    const int npj = g_npj[b];
    const int njc = (npj + 31) >> 5;
    const int jcap = min(Nn, (njc + 1) * 32);
    const int rb = blockIdx.x * ROWS_PER_BLOCK;

    if (rb < npj) {   // block-uniform
        const float4* gp = (const float4*)&g_P[b * Nn];
        const float4* gq = (const float4*)&g_Q[b * Nn];
        const float4* ga = (const float4*)&g_AC[b * Nn];
        float4* sp = (float4*)s_P;
        float4* sq = (float4*)s_Q;
        float4* sa = (float4*)s_AC;
        for (int i = tid; i < jcap; i += THREADS) { sp[i] = gp[i]; sq[i] = gq[i]; }
        for (int i = tid; i < jcap / 2; i += THREADS) sa[i] = ga[i];
        __syncthreads();
    }

    const int p0 = rb + w * RPT;
    const float2 rgv = g_range[b];
    const float vmin = rgv.x;
    const float invh = (rgv.y > vmin) ? (float)(KNOD - 1) / (rgv.y - vmin) : 0.f;

    if (p0 < npj) {
        // ---- loop path ----
        const int cls0 = (p0 + RPT <= npj);

        u64c px2[NPAIR], py2[NPAIR], pz2[NPAIR], sq2[NPAIR], nrm2[NPAIR], rg2[NPAIR];
        u64c sum2[NPAIR], cx2[NPAIR], cy2[NPAIR], cz2[NPAIR];
        #pragma unroll
        for (int t = 0; t < NPAIR; t++) {
            int pa = p0 + 2 * t, pb_ = pa + 1;
            float4 Pa = s_P[pa], Pb = s_P[pb_];
            px2[t] = pk2(-0.5f * Pa.x, -0.5f * Pb.x);
            py2[t] = pk2(-0.5f * Pa.y, -0.5f * Pb.y);
            pz2[t] = pk2(-0.5f * Pa.z, -0.5f * Pb.z);
            sq2[t] = pk2(Pa.w, Pb.w);
            float4 Qa = s_Q[pa], Qb = s_Q[pb_];
            float na = sqrtf(fmaf(Qa.x, Qa.x, fmaf(Qa.y, Qa.y, Qa.z * Qa.z)));
            float nb = sqrtf(fmaf(Qb.x, Qb.x, fmaf(Qb.y, Qb.y, Qb.z * Qb.z)));
            nrm2[t] = pk2(na, nb);
            rg2[t] = pk2((pa < npj) ? 1.f : 0.f, (pb_ < npj) ? 1.f : 0.f);
            sum2[t] = 0ull; cx2[t] = 0ull; cy2[t] = 0ull; cz2[t] = 0ull;
        }

        if (cls0) {
            #pragma unroll 2
            for (int jj = 0; jj < njc; jj++) {
                const int j = jj * 32 + lane;
                const float2 AC = s_AC[j];
                const float4 P  = s_P[j];
                const float4 Q  = s_Q[j];
                u64c A2 = pk2(AC.x, AC.x), C2 = pk2(AC.y, AC.y);
                u64c Px2 = pk2(P.x, P.x), Py2 = pk2(P.y, P.y);
                u64c Pz2 = pk2(P.z, P.z), Pw2 = pk2(P.w, P.w);
                u64c Qx2 = pk2(Q.x, Q.x), Qy2 = pk2(Q.y, Q.y), Qz2 = pk2(Q.z, Q.z);
                u64c cb2 = pk2(Q.w, Q.w);
                #pragma unroll
                for (int t = 0; t < NPAIR; t++) {
                    u64c tt = fma2_(Pz2, pz2[t], Pw2);
                    tt = fma2_(Py2, py2[t], tt);
                    tt = fma2_(Px2, px2[t], tt);
                    u64c d2 = add2_(sq2[t], tt);
                    float da, db; upk2(da, db, d2);
                    float ra = sqrtf_(fmaxf(da, 1e-12f));
                    float rb_ = sqrtf_(fmaxf(db, 1e-12f));
                    u64c s2 = fma2_(nrm2[t], A2, C2);
                    s2 = fma2_(cb2, pk2(ra, rb_), s2);
                    float sa, sb; upk2(sa, sb, s2);
                    u64c e2 = pk2(ex2f_(sa), ex2f_(sb));
                    sum2[t] = add2_(sum2[t], e2);
                    cx2[t] = fma2_(e2, Qx2, cx2[t]);
                    cy2[t] = fma2_(e2, Qy2, cy2[t]);
                    cz2[t] = fma2_(e2, Qz2, cz2[t]);
                }
            }
        } else {
            #pragma unroll 2
            for (int jj = 0; jj < njc; jj++) {
                const int j = jj * 32 + lane;
                const float2 AC = s_AC[j];
                const float4 P  = s_P[j];
                const float4 Q  = s_Q[j];
                u64c A2 = pk2(AC.x, AC.x), C2 = pk2(AC.y, AC.y);
                u64c Px2 = pk2(P.x, P.x), Py2 = pk2(P.y, P.y);
                u64c Pz2 = pk2(P.z, P.z), Pw2 = pk2(P.w, P.w);
                u64c Qx2 = pk2(Q.x, Q.x), Qy2 = pk2(Q.y, Q.y), Qz2 = pk2(Q.z, Q.z);
                u64c cb2 = pk2(Q.w, Q.w);
                #pragma unroll
                for (int t = 0; t < NPAIR; t++) {
                    u64c tt = fma2_(Pz2, pz2[t], Pw2);
                    tt = fma2_(Py2, py2[t], tt);
                    tt = fma2_(Px2, px2[t], tt);
                    u64c d2 = add2_(sq2[t], tt);
                    float da, db; upk2(da, db, d2);
                    float ra = sqrtf_(fmaxf(da, 1e-12f));
                    float rb_ = sqrtf_(fmaxf(db, 1e-12f));
                    u64c cbt = mul2_(cb2, rg2[t]);
                    u64c s2 = fma2_(nrm2[t], A2, C2);
                    s2 = fma2_(cbt, pk2(ra, rb_), s2);
                    float sa, sb; upk2(sa, sb, s2);
                    u64c e2 = pk2(ex2f_(sa), ex2f_(sb));
                    sum2[t] = add2_(sum2[t], e2);
                    cx2[t] = fma2_(e2, Qx2, cx2[t]);
                    cy2[t] = fma2_(e2, Qy2, cy2[t]);
                    cz2[t] = fma2_(e2, Qz2, cz2[t]);
                }
            }
        }

        float sum[RPT], cx[RPT], cy[RPT], cz[RPT];
        #pragma unroll
        for (int t = 0; t < NPAIR; t++) {
            upk2(sum[2 * t], sum[2 * t + 1], sum2[t]);
            upk2(cx[2 * t],  cx[2 * t + 1],  cx2[t]);
            upk2(cy[2 * t],  cy[2 * t + 1],  cy2[t]);
            upk2(cz[2 * t],  cz[2 * t + 1],  cz2[t]);
        }
        #pragma unroll
        for (int r = 0; r < RPT; r++) {
            #pragma unroll
            for (int o = 16; o > 0; o >>= 1) {
                sum[r] += __shfl_xor_sync(0xFFFFFFFFu, sum[r], o);
                cx[r]  += __shfl_xor_sync(0xFFFFFFFFu, cx[r], o);
                cy[r]  += __shfl_xor_sync(0xFFFFFFFFu, cy[r], o);
                cz[r]  += __shfl_xor_sync(0xFFFFFFFFu, cz[r], o);
            }
        }

        #pragma unroll
        for (int r = 0; r < RPT; r++) {
            if (lane == r) {
                int pi = p0 + r;
                float4 Q = s_Q[pi];
                float4 P = s_P[pi];
                float nrm = sqrtf(fmaf(Q.x, Q.x, fmaf(Q.y, Q.y, Q.z * Q.z)));
                float S = sum[r], X = cx[r], Y = cy[r], Z = cz[r];
                float rgf = (pi < npj) ? 1.f : 0.f;
                float cbw = Q.w * rgf;
                float pxi = -0.5f * P.x, pyi = -0.5f * P.y, pzi = -0.5f * P.z;
                float e_wrong = pair_term(s_AC[pi], P, cbw, pxi, pyi, pzi, P.w, nrm);
                float e_right = ex2f_(fmaf(nrm, s_AC[pi].x, s_AC[pi].y));
                float d = e_right - e_wrong;
                S += d; X = fmaf(d, Q.x, X); Y = fmaf(d, Q.y, Y); Z = fmaf(d, Q.z, Z);
                float4 tc = interp4(&g_tblCh[b * KNOD], nrm, vmin, invh);
                S += tc.x; X += tc.y; Y += tc.z; Z += tc.w;

                int oi = g_oidx[b * Nn + pi];
                int gi = b * Nn + oi;
                float nn = g_nn[b * Nn + pi];
                float f = nn / (S * (nrm + 1e-5f));
                out[gi * 3 + 0] = Q.x * X * f;
                out[gi * 3 + 1] = Q.y * Y * f;
                out[gi * 3 + 2] = Q.z * Z * f;
            }
        }
    } else {
        // ---- pure table path ----
        if (lane < RPT) {
            int pi = p0 + lane;
            float4 Q = g_Q[b * Nn + pi];
            float nrm = sqrtf(fmaf(Q.x, Q.x, fmaf(Q.y, Q.y, Q.z * Q.z)));
            float4 tp = interp4(&g_tblPh[b * KNOD], nrm, vmin, invh);
            float4 tc = interp4(&g_tblCh[b * KNOD], nrm, vmin, invh);
            float S = tp.x + tc.x, X = tp.y + tc.y, Y = tp.z + tc.z, Z = tp.w + tc.w;
            int oi = g_oidx[b * Nn + pi];
            int gi = b * Nn + oi;
            float nn = g_nn[b * Nn + pi];
            float f = nn / (S * (nrm + 1e-5f));
            out[gi * 3 + 0] = Q.x * X * f;
            out[gi * 3 + 1] = Q.y * Y * f;
            out[gi * 3 + 2] = Q.z * Z * f;
        }
    }

    // fused per-batch mean subtraction (last block of batch)
    __threadfence();
    __syncthreads();
    if (tid == 0) s_tk = atomicAdd(&g_cnt[b], 1);
    __syncthreads();
    if (s_tk == GRIDX - 1) {
        __threadfence();
        float ax = 0.f, ay = 0.f, az = 0.f;
        for (int n = tid; n < Nn; n += THREADS) {
            const float* o = out + ((size_t)b * Nn + n) * 3;
            ax += o[0]; ay += o[1]; az += o[2];
        }
        float* comps[3] = {&ax, &ay, &az};
        #pragma unroll
        for (int c = 0; c < 3; c++) {
            float v = *comps[c];
            #pragma unroll
            for (int o = 16; o > 0; o >>= 1) v += __shfl_xor_sync(0xFFFFFFFFu, v, o);
            if (lane == 0) s_red[w] = v;
            __syncthreads();
            if (tid == 0) {
                float t = 0.f;
                #pragma unroll
                for (int k = 0; k < WARPS; k++) t += s_red[k];
                s_mean[c] = t * (1.f / Nn);
            }
            __syncthreads();
        }
        float mx = s_mean[0], my = s_mean[1], mz = s_mean[2];
        for (int n = tid; n < Nn; n += THREADS) {
            float* o = out + ((size_t)b * Nn + n) * 3;
            o[0] -= mx; o[1] -= my; o[2] -= mz;
        }
        if (tid == 0) atomicExch(&g_cnt[b], 0);
    }
}

extern "C" void kernel_launch(void* const* d_in, const int* in_sizes, int n_in,
                              void* d_out, int out_size) {
    const float* pos       = (const float*)d_in[0];
    const void*  node_mask = d_in[1];
    const float* p         = (const float*)d_in[2];
    const void*  pharma    = d_in[3];
    const float* lin1_w    = (const float*)d_in[4];
    const float* lin1_b    = (const float*)d_in[5];
    const float* lin2_w    = (const float*)d_in[6];
    const float* lin2_b    = (const float*)d_in[7];
    const float* wp        = (const float*)d_in[8];
    const float* bp        = (const float*)d_in[9];
    const float* wd        = (const float*)d_in[10];
    const float* wc        = (const float*)d_in[12];

    dim3 pgrid(PREB, Bb);            // (4, 32), 1024 threads
    prep_kernel<<<pgrid, 1024>>>(pos, node_mask, p, pharma,
                                 lin1_w, lin1_b, lin2_w, lin2_b,
                                 wp, bp, wd, wc);

    dim3 grid(GRIDX, Bb);
    attn_kernel<<<grid, THREADS>>>((float*)d_out);
}

// round 14
// speedup vs baseline: 1.1813x; 1.1480x over previous
#include <cuda_runtime.h>

#define Bb 32
#define Nn 1024
#define Hh 128
#define THREADS 256
#define WARPS 8
#define RPT 4
#define NPAIR 2
#define ROWS_PER_BLOCK (WARPS * RPT)  // 32
#define GRIDX (Nn / ROWS_PER_BLOCK)   // 32
#define KMOM 8
#define NU0 1.6f
#define LN2F 0.69314718056f

__device__ int   g_cnt[Bb];    // per-batch tickets (reset after use)

// precomputed, pharma-first reordered per batch
__device__ float2 g_AC[Bb * Nn];
__device__ float4 g_P[Bb * Nn];
__device__ float4 g_Q[Bb * Nn];
__device__ float  g_nn[Bb * Nn];
__device__ int    g_oidx[Bb * Nn];
__device__ int    g_npj[Bb];

// per-batch cheap-sum moments: [b][seg][k] float4, seg0 = j<njc32, seg1 = rest
__device__ float4 g_mom[Bb * 2 * KMOM];

typedef unsigned long long u64c;

__device__ __forceinline__ float ex2f_(float x) {
    float y; asm("ex2.approx.ftz.f32 %0, %1;" : "=f"(y) : "f"(x)); return y;
}
__device__ __forceinline__ float sqrtf_(float x) {
    float y; asm("sqrt.approx.ftz.f32 %0, %1;" : "=f"(y) : "f"(x)); return y;
}
__device__ __forceinline__ bool mask_at(const void* m, int idx, int isByte) {
    if (isByte) return ((const unsigned char*)m)[idx] != 0;
    return ((const int*)m)[idx] != 0;
}

__device__ __forceinline__ u64c pk2(float lo, float hi) {
    u64c r; asm("mov.b64 %0, {%1, %2};" : "=l"(r) : "f"(lo), "f"(hi)); return r;
}
__device__ __forceinline__ void upk2(float& lo, float& hi, u64c v) {
    asm("mov.b64 {%0, %1}, %2;" : "=f"(lo), "=f"(hi) : "l"(v));
}
__device__ __forceinline__ u64c fma2_(u64c a, u64c b, u64c c) {
    u64c r; asm("fma.rn.f32x2 %0, %1, %2, %3;" : "=l"(r) : "l"(a), "l"(b), "l"(c)); return r;
}
__device__ __forceinline__ u64c add2_(u64c a, u64c b) {
    u64c r; asm("add.rn.f32x2 %0, %1, %2;" : "=l"(r) : "l"(a), "l"(b)); return r;
}
__device__ __forceinline__ u64c mul2_(u64c a, u64c b) {
    u64c r; asm("mul.rn.f32x2 %0, %1, %2;" : "=l"(r) : "l"(a), "l"(b)); return r;
}

__device__ __forceinline__ float pair_term(float2 AC, float4 P, float cbw,
                                           float pxi, float pyi, float pzi,
                                           float sqi, float nrm) {
    float t = fmaf(P.z, pzi, P.w);
    t = fmaf(P.y, pyi, t);
    t = fmaf(P.x, pxi, t);
    float d2 = fmaxf(sqi + t, 1e-12f);
    float dist = sqrtf_(d2);
    float s = fmaf(nrm, AC.x, AC.y);
    s = fmaf(cbw, dist, s);
    return ex2f_(s);
}

// Horner evaluation of the K-term moment polynomial at delta = nu - NU0.
__device__ __forceinline__ float4 mom_eval(const float4* __restrict__ m, float d) {
    float4 a = m[KMOM - 1];
    #pragma unroll
    for (int k = KMOM - 2; k >= 0; k--) {
        a.x = fmaf(a.x, d, m[k].x);
        a.y = fmaf(a.y, d, m[k].y);
        a.z = fmaf(a.z, d, m[k].z);
        a.w = fmaf(a.w, d, m[k].w);
    }
    return a;
}

// ---------------------------------------------------------------------------
// Precompute (R10 form, grid (4,Bb) x 256): mask detect, 9-scalar collapse,
// pharma-first reorder + SoA + gated MLP.
// ---------------------------------------------------------------------------
__global__ __launch_bounds__(THREADS)
void pre_kernel(const float* __restrict__ pos,
                const void* __restrict__ node_mask,
                const float* __restrict__ p,
                const void* __restrict__ pharma,
                const float* __restrict__ lin1_w,
                const float* __restrict__ lin1_b,
                const float* __restrict__ lin2_w,
                const float* __restrict__ lin2_b,
                const float* __restrict__ wp,
                const float* __restrict__ bp,
                const float* __restrict__ wd,
                const float* __restrict__ wc) {
    __shared__ int   s_chk[32];
    __shared__ int   s_npj;
    __shared__ float s_l1w[Hh], s_l1b[Hh], s_l2w[Hh];
    __shared__ float s_prm[9];

    const int b = blockIdx.y;
    const int q = blockIdx.x;
    const int tid = threadIdx.x;
    const int w = tid >> 5;
    const int lane = tid & 31;

    if (tid < Hh) {
        s_l1w[tid] = lin1_w[tid];
        s_l1b[tid] = lin1_b[tid];
        s_l2w[tid] = lin2_w[tid];
    }

    int any = (tid < 256) && (((const unsigned int*)node_mask)[tid] > 1u);
    const int isB = __syncthreads_or(any) ? 1 : 0;

    if (w == 0) {
        const float L2E = 1.4426950408889634f;
        float u0 = 0.f, u1 = 0.f, u2 = 0.f, au = 0.f;
        float v0 = 0.f, v1 = 0.f, v2 = 0.f, av = 0.f, kd = 0.f;
        for (int h = lane; h < Hh; h += 32) {
            float w1h = wc[h];
            float w2h = wc[Hh + h];
            float a = lin1_w[h] * w1h;
            float c = lin1_b[h] * w1h;
            float wp0 = wp[h * 3 + 0], wp1 = wp[h * 3 + 1], wp2 = wp[h * 3 + 2];
            u0 = fmaf(a, wp0, u0); u1 = fmaf(a, wp1, u1); u2 = fmaf(a, wp2, u2);
            au = fmaf(a, bp[h], au);
            v0 = fmaf(c, wp0, v0); v1 = fmaf(c, wp1, v1); v2 = fmaf(c, wp2, v2);
            av = fmaf(c, bp[h], av);
            kd = fmaf(wd[h], w2h, kd);
        }
        #pragma unroll
        for (int o = 16; o > 0; o >>= 1) {
            u0 += __shfl_xor_sync(0xFFFFFFFFu, u0, o);
            u1 += __shfl_xor_sync(0xFFFFFFFFu, u1, o);
            u2 += __shfl_xor_sync(0xFFFFFFFFu, u2, o);
            au += __shfl_xor_sync(0xFFFFFFFFu, au, o);
            v0 += __shfl_xor_sync(0xFFFFFFFFu, v0, o);
            v1 += __shfl_xor_sync(0xFFFFFFFFu, v1, o);
            v2 += __shfl_xor_sync(0xFFFFFFFFu, v2, o);
            av += __shfl_xor_sync(0xFFFFFFFFu, av, o);
            kd += __shfl_xor_sync(0xFFFFFFFFu, kd, o);
        }
        if (lane == 0) {
            s_prm[0] = u0 * L2E; s_prm[1] = u1 * L2E; s_prm[2] = u2 * L2E; s_prm[3] = au * L2E;
            s_prm[4] = v0 * L2E; s_prm[5] = v1 * L2E; s_prm[6] = v2 * L2E; s_prm[7] = av * L2E;
            s_prm[8] = kd * L2E;
        }
    }

    #pragma unroll
    for (int k = 0; k < Nn / THREADS; k++) {
        int j = k * THREADS + tid;
        bool ph = mask_at(pharma, b * Nn + j, isB);
        unsigned m = __ballot_sync(0xFFFFFFFFu, ph);
        if (lane == 0) s_chk[k * WARPS + w] = __popc(m);
    }
    __syncthreads();
    if (tid < 32) {
        int v = s_chk[tid];
        int incl = v;
        #pragma unroll
        for (int o = 1; o < 32; o <<= 1) {
            int t = __shfl_up_sync(0xFFFFFFFFu, incl, o);
            if (lane >= o) incl += t;
        }
        s_chk[tid] = incl - v;
        if (tid == 31) s_npj = incl;
    }
    __syncthreads();
    const int npj = s_npj;

    const float u0 = s_prm[0], u1 = s_prm[1], u2 = s_prm[2], au = s_prm[3];
    const float v0 = s_prm[4], v1 = s_prm[5], v2 = s_prm[6], av = s_prm[7];
    const float kdL = s_prm[8];
    const float l2b = lin2_b[0];

    {
        int j = q * THREADS + tid;
        bool ph = mask_at(pharma, b * Nn + j, isB);
        unsigned m = __ballot_sync(0xFFFFFFFFu, ph);
        unsigned below = m & ((1u << lane) - 1u);
        int c = q * WARPS + w;
        int phOff = s_chk[c];
        int pos_;
        if (ph) pos_ = phOff + __popc(below);
        else    pos_ = npj + (c * 32 - phOff) + (lane - __popc(below));

        const float* posb = pos + (size_t)b * Nn * 3;
        const float* pb   = p   + (size_t)b * Nn * 3;
        float qx = posb[j * 3 + 0], qy = posb[j * 3 + 1], qz = posb[j * 3 + 2];
        float A = fmaf(qx, u0, fmaf(qy, u1, fmaf(qz, u2, au)));
        float C = fmaf(qx, v0, fmaf(qy, v1, fmaf(qz, v2, av)));
        float px = pb[j * 3 + 0], py = pb[j * 3 + 1], pz = pb[j * 3 + 2];
        float sq = fmaf(px, px, fmaf(py, py, pz * pz));

        int gp = b * Nn + pos_;
        g_AC[gp] = make_float2(A, C);
        g_P[gp]  = make_float4(-2.f * px, -2.f * py, -2.f * pz, sq);
        g_Q[gp]  = make_float4(qx, qy, qz, ph ? kdL : 0.f);
        g_oidx[gp] = j;

        float nrm = sqrtf(fmaf(qx, qx, fmaf(qy, qy, qz * qz)));
        float nn = 0.f;
        #pragma unroll 8
        for (int h = 0; h < Hh; h++) {
            float hid = fmaf(nrm, s_l1w[h], s_l1b[h]);
            nn = fmaf(fmaxf(hid, 0.f), s_l2w[h], nn);
        }
        bool node = mask_at(node_mask, b * Nn + j, isB);
        g_nn[gp] = node ? (nn + l2b) : 0.f;
    }

    if (q == 0 && tid == 0) g_npj[b] = npj;
}

// ---------------------------------------------------------------------------
// Moment kernel: grid (Bb) x 1024, one j per thread. Two-segment K-term
// moments of the cheap-form sums about NU0. Deterministic two-stage reduce.
// ---------------------------------------------------------------------------
__global__ __launch_bounds__(1024)
void mom_kernel() {
    __shared__ float4 s_part[32][2 * KMOM];   // per warp

    const int b = blockIdx.x;
    const int tid = threadIdx.x;
    const int w = tid >> 5;
    const int lane = tid & 31;
    const int j = tid;

    const int npj = g_npj[b];
    const int njc32 = ((npj + 31) >> 5) << 5;
    const int seg = (j < njc32) ? 0 : 1;   // warp-uniform (njc32 is 32-aligned)

    float2 ac = g_AC[b * Nn + j];
    float4 q  = g_Q[b * Nn + j];

    float e = ex2f_(fmaf(NU0, ac.x, ac.y));
    float t = ac.x * LN2F;

    float4 m[KMOM];
    float wk = e;
    m[0] = make_float4(wk, wk * q.x, wk * q.y, wk * q.z);
    #pragma unroll
    for (int k = 1; k < KMOM; k++) {
        wk *= t * (1.f / (float)k);
        m[k] = make_float4(wk, wk * q.x, wk * q.y, wk * q.z);
    }

    // warp reduce all KMOM float4s
    #pragma unroll
    for (int k = 0; k < KMOM; k++) {
        #pragma unroll
        for (int o = 16; o > 0; o >>= 1) {
            m[k].x += __shfl_xor_sync(0xFFFFFFFFu, m[k].x, o);
            m[k].y += __shfl_xor_sync(0xFFFFFFFFu, m[k].y, o);
            m[k].z += __shfl_xor_sync(0xFFFFFFFFu, m[k].z, o);
            m[k].w += __shfl_xor_sync(0xFFFFFFFFu, m[k].w, o);
        }
    }
    if (lane == 0) {
        #pragma unroll
        for (int k = 0; k < KMOM; k++) {
            s_part[w][seg * KMOM + k] = m[k];
            s_part[w][(1 - seg) * KMOM + k] = make_float4(0.f, 0.f, 0.f, 0.f);
        }
    }
    __syncthreads();

    // final: threads 0..2*KMOM-1 each sum one slot over 32 warps (fixed order)
    if (tid < 2 * KMOM) {
        float4 acc = make_float4(0.f, 0.f, 0.f, 0.f);
        #pragma unroll
        for (int k = 0; k < 32; k++) {
            float4 v = s_part[k][tid];
            acc.x += v.x; acc.y += v.y; acc.z += v.z; acc.w += v.w;
        }
        g_mom[b * 2 * KMOM + tid] = acc;
    }
}

// ---------------------------------------------------------------------------
// Main kernel: pharma rows = exact dist loop over j<njc32 + ch-moment poly;
// cheap rows = ph+ch moment polys.
// ---------------------------------------------------------------------------
__global__ __launch_bounds__(THREADS, 3)
void attn_kernel(float* __restrict__ out) {
    __shared__ float2 s_AC[Nn];
    __shared__ float4 s_P[Nn];
    __shared__ float4 s_Q[Nn];
    __shared__ float4 s_mom[2 * KMOM];
    __shared__ float  s_red[WARPS];
    __shared__ float  s_mean[3];
    __shared__ int    s_tk;

    const int b = blockIdx.y;
    const int tid = threadIdx.x;
    const int w = tid >> 5;
    const int lane = tid & 31;

    const int npj = g_npj[b];
    const int njc = (npj + 31) >> 5;
    const int jcap = min(Nn, (njc + 1) * 32);
    const int rb = blockIdx.x * ROWS_PER_BLOCK;

    if (tid < 2 * KMOM) s_mom[tid] = g_mom[b * 2 * KMOM + tid];

    if (rb < npj) {   // loop-path blocks copy the exact-segment SoA
        const float4* gp = (const float4*)&g_P[b * Nn];
        const float4* gq = (const float4*)&g_Q[b * Nn];
        const float4* ga = (const float4*)&g_AC[b * Nn];
        float4* sp = (float4*)s_P;
        float4* sq = (float4*)s_Q;
        float4* sa = (float4*)s_AC;
        for (int i = tid; i < jcap; i += THREADS) { sp[i] = gp[i]; sq[i] = gq[i]; }
        for (int i = tid; i < jcap / 2; i += THREADS) sa[i] = ga[i];
    }
    __syncthreads();

    const int p0 = rb + w * RPT;

    if (p0 < npj) {
        // ---- loop path ----
        const int cls0 = (p0 + RPT <= npj);

        u64c px2[NPAIR], py2[NPAIR], pz2[NPAIR], sq2[NPAIR], nrm2[NPAIR], rg2[NPAIR];
        u64c sum2[NPAIR], cx2[NPAIR], cy2[NPAIR], cz2[NPAIR];
        #pragma unroll
        for (int t = 0; t < NPAIR; t++) {
            int pa = p0 + 2 * t, pb_ = pa + 1;
            float4 Pa = s_P[pa], Pb = s_P[pb_];
            px2[t] = pk2(-0.5f * Pa.x, -0.5f * Pb.x);
            py2[t] = pk2(-0.5f * Pa.y, -0.5f * Pb.y);
            pz2[t] = pk2(-0.5f * Pa.z, -0.5f * Pb.z);
            sq2[t] = pk2(Pa.w, Pb.w);
            float4 Qa = s_Q[pa], Qb = s_Q[pb_];
            float na = sqrtf(fmaf(Qa.x, Qa.x, fmaf(Qa.y, Qa.y, Qa.z * Qa.z)));
            float nb = sqrtf(fmaf(Qb.x, Qb.x, fmaf(Qb.y, Qb.y, Qb.z * Qb.z)));
            nrm2[t] = pk2(na, nb);
            rg2[t] = pk2((pa < npj) ? 1.f : 0.f, (pb_ < npj) ? 1.f : 0.f);
            sum2[t] = 0ull; cx2[t] = 0ull; cy2[t] = 0ull; cz2[t] = 0ull;
        }

        if (cls0) {
            #pragma unroll 2
            for (int jj = 0; jj < njc; jj++) {
                const int j = jj * 32 + lane;
                const float2 AC = s_AC[j];
                const float4 P  = s_P[j];
                const float4 Q  = s_Q[j];
                u64c A2 = pk2(AC.x, AC.x), C2 = pk2(AC.y, AC.y);
                u64c Px2 = pk2(P.x, P.x), Py2 = pk2(P.y, P.y);
                u64c Pz2 = pk2(P.z, P.z), Pw2 = pk2(P.w, P.w);
                u64c Qx2 = pk2(Q.x, Q.x), Qy2 = pk2(Q.y, Q.y), Qz2 = pk2(Q.z, Q.z);
                u64c cb2 = pk2(Q.w, Q.w);
                #pragma unroll
                for (int t = 0; t < NPAIR; t++) {
                    u64c tt = fma2_(Pz2, pz2[t], Pw2);
                    tt = fma2_(Py2, py2[t], tt);
                    tt = fma2_(Px2, px2[t], tt);
                    u64c d2 = add2_(sq2[t], tt);
                    float da, db; upk2(da, db, d2);
                    float ra = sqrtf_(fmaxf(da, 1e-12f));
                    float rb_ = sqrtf_(fmaxf(db, 1e-12f));
                    u64c s2 = fma2_(nrm2[t], A2, C2);
                    s2 = fma2_(cb2, pk2(ra, rb_), s2);
                    float sa, sb; upk2(sa, sb, s2);
                    u64c e2 = pk2(ex2f_(sa), ex2f_(sb));
                    sum2[t] = add2_(sum2[t], e2);
                    cx2[t] = fma2_(e2, Qx2, cx2[t]);
                    cy2[t] = fma2_(e2, Qy2, cy2[t]);
                    cz2[t] = fma2_(e2, Qz2, cz2[t]);
                }
            }
        } else {
            #pragma unroll 2
            for (int jj = 0; jj < njc; jj++) {
                const int j = jj * 32 + lane;
                const float2 AC = s_AC[j];
                const float4 P  = s_P[j];
                const float4 Q  = s_Q[j];
                u64c A2 = pk2(AC.x, AC.x), C2 = pk2(AC.y, AC.y);
                u64c Px2 = pk2(P.x, P.x), Py2 = pk2(P.y, P.y);
                u64c Pz2 = pk2(P.z, P.z), Pw2 = pk2(P.w, P.w);
                u64c Qx2 = pk2(Q.x, Q.x), Qy2 = pk2(Q.y, Q.y), Qz2 = pk2(Q.z, Q.z);
                u64c cb2 = pk2(Q.w, Q.w);
                #pragma unroll
                for (int t = 0; t < NPAIR; t++) {
                    u64c tt = fma2_(Pz2, pz2[t], Pw2);
                    tt = fma2_(Py2, py2[t], tt);
                    tt = fma2_(Px2, px2[t], tt);
                    u64c d2 = add2_(sq2[t], tt);
                    float da, db; upk2(da, db, d2);
                    float ra = sqrtf_(fmaxf(da, 1e-12f));
                    float rb_ = sqrtf_(fmaxf(db, 1e-12f));
                    u64c cbt = mul2_(cb2, rg2[t]);
                    u64c s2 = fma2_(nrm2[t], A2, C2);
                    s2 = fma2_(cbt, pk2(ra, rb_), s2);
                    float sa, sb; upk2(sa, sb, s2);
                    u64c e2 = pk2(ex2f_(sa), ex2f_(sb));
                    sum2[t] = add2_(sum2[t], e2);
                    cx2[t] = fma2_(e2, Qx2, cx2[t]);
                    cy2[t] = fma2_(e2, Qy2, cy2[t]);
                    cz2[t] = fma2_(e2, Qz2, cz2[t]);
                }
            }
        }

        float sum[RPT], cx[RPT], cy[RPT], cz[RPT];
        #pragma unroll
        for (int t = 0; t < NPAIR; t++) {
            upk2(sum[2 * t], sum[2 * t + 1], sum2[t]);
            upk2(cx[2 * t],  cx[2 * t + 1],  cx2[t]);
            upk2(cy[2 * t],  cy[2 * t + 1],  cy2[t]);
            upk2(cz[2 * t],  cz[2 * t + 1],  cz2[t]);
        }
        #pragma unroll
        for (int r = 0; r < RPT; r++) {
            #pragma unroll
            for (int o = 16; o > 0; o >>= 1) {
                sum[r] += __shfl_xor_sync(0xFFFFFFFFu, sum[r], o);
                cx[r]  += __shfl_xor_sync(0xFFFFFFFFu, cx[r], o);
                cy[r]  += __shfl_xor_sync(0xFFFFFFFFu, cy[r], o);
                cz[r]  += __shfl_xor_sync(0xFFFFFFFFu, cz[r], o);
            }
        }

        #pragma unroll
        for (int r = 0; r < RPT; r++) {
            if (lane == r) {
                int pi = p0 + r;
                float4 Q = s_Q[pi];
                float4 P = s_P[pi];
                float nrm = sqrtf(fmaf(Q.x, Q.x, fmaf(Q.y, Q.y, Q.z * Q.z)));
                float S = sum[r], X = cx[r], Y = cy[r], Z = cz[r];
                float rgf = (pi < npj) ? 1.f : 0.f;
                float cbw = Q.w * rgf;
                float pxi = -0.5f * P.x, pyi = -0.5f * P.y, pzi = -0.5f * P.z;
                float e_wrong = pair_term(s_AC[pi], P, cbw, pxi, pyi, pzi, P.w, nrm);
                float e_right = ex2f_(fmaf(nrm, s_AC[pi].x, s_AC[pi].y));
                float d = e_right - e_wrong;
                S += d; X = fmaf(d, Q.x, X); Y = fmaf(d, Q.y, Y); Z = fmaf(d, Q.z, Z);
                // cheap segment via ch-moment polynomial
                float4 tc = mom_eval(&s_mom[KMOM], nrm - NU0);
                S += tc.x; X += tc.y; Y += tc.z; Z += tc.w;

                int oi = g_oidx[b * Nn + pi];
                int gi = b * Nn + oi;
                float nn = g_nn[b * Nn + pi];
                float f = nn / (S * (nrm + 1e-5f));
                out[gi * 3 + 0] = Q.x * X * f;
                out[gi * 3 + 1] = Q.y * Y * f;
                out[gi * 3 + 2] = Q.z * Z * f;
            }
        }
    } else {
        // ---- pure moment path ----
        if (lane < RPT) {
            int pi = p0 + lane;
            float4 Q = g_Q[b * Nn + pi];
            float nrm = sqrtf(fmaf(Q.x, Q.x, fmaf(Q.y, Q.y, Q.z * Q.z)));
            float dlt = nrm - NU0;
            float4 tp = mom_eval(&s_mom[0], dlt);
            float4 tc = mom_eval(&s_mom[KMOM], dlt);
            float S = tp.x + tc.x, X = tp.y + tc.y, Y = tp.z + tc.z, Z = tp.w + tc.w;
            int oi = g_oidx[b * Nn + pi];
            int gi = b * Nn + oi;
            float nn = g_nn[b * Nn + pi];
            float f = nn / (S * (nrm + 1e-5f));
            out[gi * 3 + 0] = Q.x * X * f;
            out[gi * 3 + 1] = Q.y * Y * f;
            out[gi * 3 + 2] = Q.z * Z * f;
        }
    }

    // fused per-batch mean subtraction (last block of batch)
    __threadfence();
    __syncthreads();
    if (tid == 0) s_tk = atomicAdd(&g_cnt[b], 1);
    __syncthreads();
    if (s_tk == GRIDX - 1) {
        __threadfence();
        float ax = 0.f, ay = 0.f, az = 0.f;
        for (int n = tid; n < Nn; n += THREADS) {
            const float* o = out + ((size_t)b * Nn + n) * 3;
            ax += o[0]; ay += o[1]; az += o[2];
        }
        float* comps[3] = {&ax, &ay, &az};
        #pragma unroll
        for (int c = 0; c < 3; c++) {
            float v = *comps[c];
            #pragma unroll
            for (int o = 16; o > 0; o >>= 1) v += __shfl_xor_sync(0xFFFFFFFFu, v, o);
            if (lane == 0) s_red[w] = v;
            __syncthreads();
            if (tid == 0) {
                float t = 0.f;
                #pragma unroll
                for (int k = 0; k < WARPS; k++) t += s_red[k];
                s_mean[c] = t * (1.f / Nn);
            }
            __syncthreads();
        }
        float mx = s_mean[0], my = s_mean[1], mz = s_mean[2];
        for (int n = tid; n < Nn; n += THREADS) {
            float* o = out + ((size_t)b * Nn + n) * 3;
            o[0] -= mx; o[1] -= my; o[2] -= mz;
        }
        if (tid == 0) atomicExch(&g_cnt[b], 0);
    }
}

extern "C" void kernel_launch(void* const* d_in, const int* in_sizes, int n_in,
                              void* d_out, int out_size) {
    const float* pos       = (const float*)d_in[0];
    const void*  node_mask = d_in[1];
    const float* p         = (const float*)d_in[2];
    const void*  pharma    = d_in[3];
    const float* lin1_w    = (const float*)d_in[4];
    const float* lin1_b    = (const float*)d_in[5];
    const float* lin2_w    = (const float*)d_in[6];
    const float* lin2_b    = (const float*)d_in[7];
    const float* wp        = (const float*)d_in[8];
    const float* bp        = (const float*)d_in[9];
    const float* wd        = (const float*)d_in[10];
    const float* wc        = (const float*)d_in[12];

    dim3 pgrid(Nn / THREADS, Bb);   // (4, 32)
    pre_kernel<<<pgrid, THREADS>>>(pos, node_mask, p, pharma,
                                   lin1_w, lin1_b, lin2_w, lin2_b,
                                   wp, bp, wd, wc);

    mom_kernel<<<Bb, 1024>>>();

    dim3 grid(GRIDX, Bb);
    attn_kernel<<<grid, THREADS>>>((float*)d_out);
}

// round 16
// speedup vs baseline: 1.2468x; 1.0555x over previous
#include <cuda_runtime.h>

#define Bb 32
#define Nn 1024
#define Hh 128
#define THREADS 256
#define WARPS 8
#define RPT 4
#define NPAIR 2
#define ROWS_PER_BLOCK (WARPS * RPT)  // 32
#define GRIDX (Nn / ROWS_PER_BLOCK)   // 32
#define KMOM 8
#define NU0 1.6f
#define LN2F 0.69314718056f

__device__ int   g_cnt[Bb];    // per-batch tickets (reset after use)
__device__ int   g_isB;        // mask dtype flag

// precomputed, pharma-first reordered per batch
__device__ float2 g_AC[Bb * Nn];
__device__ float4 g_P[Bb * Nn];
__device__ float4 g_Q[Bb * Nn];
__device__ int    g_oidx[Bb * Nn];
__device__ int    g_npj[Bb];

// per-batch cheap-sum moments: [b][seg][k] float4, seg0 = j<njc32, seg1 = rest
__device__ float4 g_mom[Bb * 2 * KMOM];

typedef unsigned long long u64c;

__device__ __forceinline__ float ex2f_(float x) {
    float y; asm("ex2.approx.ftz.f32 %0, %1;" : "=f"(y) : "f"(x)); return y;
}
__device__ __forceinline__ float sqrtf_(float x) {
    float y; asm("sqrt.approx.ftz.f32 %0, %1;" : "=f"(y) : "f"(x)); return y;
}
__device__ __forceinline__ bool mask_at(const void* m, int idx, int isByte) {
    if (isByte) return ((const unsigned char*)m)[idx] != 0;
    return ((const int*)m)[idx] != 0;
}

__device__ __forceinline__ u64c pk2(float lo, float hi) {
    u64c r; asm("mov.b64 %0, {%1, %2};" : "=l"(r) : "f"(lo), "f"(hi)); return r;
}
__device__ __forceinline__ void upk2(float& lo, float& hi, u64c v) {
    asm("mov.b64 {%0, %1}, %2;" : "=f"(lo), "=f"(hi) : "l"(v));
}
__device__ __forceinline__ u64c fma2_(u64c a, u64c b, u64c c) {
    u64c r; asm("fma.rn.f32x2 %0, %1, %2, %3;" : "=l"(r) : "l"(a), "l"(b), "l"(c)); return r;
}
__device__ __forceinline__ u64c add2_(u64c a, u64c b) {
    u64c r; asm("add.rn.f32x2 %0, %1, %2;" : "=l"(r) : "l"(a), "l"(b)); return r;
}
__device__ __forceinline__ u64c mul2_(u64c a, u64c b) {
    u64c r; asm("mul.rn.f32x2 %0, %1, %2;" : "=l"(r) : "l"(a), "l"(b)); return r;
}

__device__ __forceinline__ float pair_term(float2 AC, float4 P, float cbw,
                                           float pxi, float pyi, float pzi,
                                           float sqi, float nrm) {
    float t = fmaf(P.z, pzi, P.w);
    t = fmaf(P.y, pyi, t);
    t = fmaf(P.x, pxi, t);
    float d2 = fmaxf(sqi + t, 1e-12f);
    float dist = sqrtf_(d2);
    float s = fmaf(nrm, AC.x, AC.y);
    s = fmaf(cbw, dist, s);
    return ex2f_(s);
}

// Horner evaluation of the K-term moment polynomial at delta = nu - NU0.
__device__ __forceinline__ float4 mom_eval(const float4* __restrict__ m, float d) {
    float4 a = m[KMOM - 1];
    #pragma unroll
    for (int k = KMOM - 2; k >= 0; k--) {
        a.x = fmaf(a.x, d, m[k].x);
        a.y = fmaf(a.y, d, m[k].y);
        a.z = fmaf(a.z, d, m[k].z);
        a.w = fmaf(a.w, d, m[k].w);
    }
    return a;
}

// ---------------------------------------------------------------------------
// Precompute (grid (4,Bb) x 256): mask detect, 9-scalar collapse, pharma-first
// reorder + SoA. MLP moved to attn epilogue.
// ---------------------------------------------------------------------------
__global__ __launch_bounds__(THREADS)
void pre_kernel(const float* __restrict__ pos,
                const void* __restrict__ node_mask,
                const float* __restrict__ p,
                const void* __restrict__ pharma,
                const float* __restrict__ lin1_w,
                const float* __restrict__ lin1_b,
                const float* __restrict__ wp,
                const float* __restrict__ bp,
                const float* __restrict__ wd,
                const float* __restrict__ wc) {
    __shared__ int   s_chk[32];
    __shared__ int   s_npj;
    __shared__ float s_prm[9];

    const int b = blockIdx.y;
    const int q = blockIdx.x;
    const int tid = threadIdx.x;
    const int w = tid >> 5;
    const int lane = tid & 31;

    int any = (tid < 256) && (((const unsigned int*)node_mask)[tid] > 1u);
    const int isB = __syncthreads_or(any) ? 1 : 0;

    if (w == 0) {
        const float L2E = 1.4426950408889634f;
        float u0 = 0.f, u1 = 0.f, u2 = 0.f, au = 0.f;
        float v0 = 0.f, v1 = 0.f, v2 = 0.f, av = 0.f, kd = 0.f;
        for (int h = lane; h < Hh; h += 32) {
            float w1h = wc[h];
            float w2h = wc[Hh + h];
            float a = lin1_w[h] * w1h;
            float c = lin1_b[h] * w1h;
            float wp0 = wp[h * 3 + 0], wp1 = wp[h * 3 + 1], wp2 = wp[h * 3 + 2];
            u0 = fmaf(a, wp0, u0); u1 = fmaf(a, wp1, u1); u2 = fmaf(a, wp2, u2);
            au = fmaf(a, bp[h], au);
            v0 = fmaf(c, wp0, v0); v1 = fmaf(c, wp1, v1); v2 = fmaf(c, wp2, v2);
            av = fmaf(c, bp[h], av);
            kd = fmaf(wd[h], w2h, kd);
        }
        #pragma unroll
        for (int o = 16; o > 0; o >>= 1) {
            u0 += __shfl_xor_sync(0xFFFFFFFFu, u0, o);
            u1 += __shfl_xor_sync(0xFFFFFFFFu, u1, o);
            u2 += __shfl_xor_sync(0xFFFFFFFFu, u2, o);
            au += __shfl_xor_sync(0xFFFFFFFFu, au, o);
            v0 += __shfl_xor_sync(0xFFFFFFFFu, v0, o);
            v1 += __shfl_xor_sync(0xFFFFFFFFu, v1, o);
            v2 += __shfl_xor_sync(0xFFFFFFFFu, v2, o);
            av += __shfl_xor_sync(0xFFFFFFFFu, av, o);
            kd += __shfl_xor_sync(0xFFFFFFFFu, kd, o);
        }
        if (lane == 0) {
            s_prm[0] = u0 * L2E; s_prm[1] = u1 * L2E; s_prm[2] = u2 * L2E; s_prm[3] = au * L2E;
            s_prm[4] = v0 * L2E; s_prm[5] = v1 * L2E; s_prm[6] = v2 * L2E; s_prm[7] = av * L2E;
            s_prm[8] = kd * L2E;
        }
    }

    #pragma unroll
    for (int k = 0; k < Nn / THREADS; k++) {
        int j = k * THREADS + tid;
        bool ph = mask_at(pharma, b * Nn + j, isB);
        unsigned m = __ballot_sync(0xFFFFFFFFu, ph);
        if (lane == 0) s_chk[k * WARPS + w] = __popc(m);
    }
    __syncthreads();
    if (tid < 32) {
        int v = s_chk[tid];
        int incl = v;
        #pragma unroll
        for (int o = 1; o < 32; o <<= 1) {
            int t = __shfl_up_sync(0xFFFFFFFFu, incl, o);
            if (lane >= o) incl += t;
        }
        s_chk[tid] = incl - v;
        if (tid == 31) s_npj = incl;
    }
    __syncthreads();
    const int npj = s_npj;

    const float u0 = s_prm[0], u1 = s_prm[1], u2 = s_prm[2], au = s_prm[3];
    const float v0 = s_prm[4], v1 = s_prm[5], v2 = s_prm[6], av = s_prm[7];
    const float kdL = s_prm[8];

    {
        int j = q * THREADS + tid;
        bool ph = mask_at(pharma, b * Nn + j, isB);
        unsigned m = __ballot_sync(0xFFFFFFFFu, ph);
        unsigned below = m & ((1u << lane) - 1u);
        int c = q * WARPS + w;
        int phOff = s_chk[c];
        int pos_;
        if (ph) pos_ = phOff + __popc(below);
        else    pos_ = npj + (c * 32 - phOff) + (lane - __popc(below));

        const float* posb = pos + (size_t)b * Nn * 3;
        const float* pb   = p   + (size_t)b * Nn * 3;
        float qx = posb[j * 3 + 0], qy = posb[j * 3 + 1], qz = posb[j * 3 + 2];
        float A = fmaf(qx, u0, fmaf(qy, u1, fmaf(qz, u2, au)));
        float C = fmaf(qx, v0, fmaf(qy, v1, fmaf(qz, v2, av)));
        float px = pb[j * 3 + 0], py = pb[j * 3 + 1], pz = pb[j * 3 + 2];
        float sq = fmaf(px, px, fmaf(py, py, pz * pz));

        int gp = b * Nn + pos_;
        g_AC[gp] = make_float2(A, C);
        g_P[gp]  = make_float4(-2.f * px, -2.f * py, -2.f * pz, sq);
        g_Q[gp]  = make_float4(qx, qy, qz, ph ? kdL : 0.f);
        g_oidx[gp] = j;
    }

    if (q == 0 && tid == 0) { g_npj[b] = npj; g_isB = isB; }
}

// ---------------------------------------------------------------------------
// Moment kernel: grid (Bb) x 1024, one j per thread. Two-segment K-term
// moments of the cheap-form sums about NU0. Deterministic two-stage reduce.
// ---------------------------------------------------------------------------
__global__ __launch_bounds__(1024)
void mom_kernel() {
    __shared__ float4 s_part[32][2 * KMOM];

    const int b = blockIdx.x;
    const int tid = threadIdx.x;
    const int w = tid >> 5;
    const int lane = tid & 31;
    const int j = tid;

    const int npj = g_npj[b];
    const int njc32 = ((npj + 31) >> 5) << 5;
    const int seg = (j < njc32) ? 0 : 1;   // warp-uniform

    float2 ac = g_AC[b * Nn + j];
    float4 q  = g_Q[b * Nn + j];

    float e = ex2f_(fmaf(NU0, ac.x, ac.y));
    float t = ac.x * LN2F;

    float4 m[KMOM];
    float wk = e;
    m[0] = make_float4(wk, wk * q.x, wk * q.y, wk * q.z);
    #pragma unroll
    for (int k = 1; k < KMOM; k++) {
        wk *= t * (1.f / (float)k);
        m[k] = make_float4(wk, wk * q.x, wk * q.y, wk * q.z);
    }

    #pragma unroll
    for (int k = 0; k < KMOM; k++) {
        #pragma unroll
        for (int o = 16; o > 0; o >>= 1) {
            m[k].x += __shfl_xor_sync(0xFFFFFFFFu, m[k].x, o);
            m[k].y += __shfl_xor_sync(0xFFFFFFFFu, m[k].y, o);
            m[k].z += __shfl_xor_sync(0xFFFFFFFFu, m[k].z, o);
            m[k].w += __shfl_xor_sync(0xFFFFFFFFu, m[k].w, o);
        }
    }
    if (lane == 0) {
        #pragma unroll
        for (int k = 0; k < KMOM; k++) {
            s_part[w][seg * KMOM + k] = m[k];
            s_part[w][(1 - seg) * KMOM + k] = make_float4(0.f, 0.f, 0.f, 0.f);
        }
    }
    __syncthreads();

    if (tid < 2 * KMOM) {
        float4 acc = make_float4(0.f, 0.f, 0.f, 0.f);
        #pragma unroll
        for (int k = 0; k < 32; k++) {
            float4 v = s_part[k][tid];
            acc.x += v.x; acc.y += v.y; acc.z += v.z; acc.w += v.w;
        }
        g_mom[b * 2 * KMOM + tid] = acc;
    }
}

// ---------------------------------------------------------------------------
// Main kernel: pharma rows = exact dist loop over j<njc32 + ch-moment poly;
// cheap rows = ph+ch moment polys. MLP computed warp-cooperatively here.
// ---------------------------------------------------------------------------
__global__ __launch_bounds__(THREADS, 3)
void attn_kernel(const void* __restrict__ node_mask,
                 const float* __restrict__ lin1_w,
                 const float* __restrict__ lin1_b,
                 const float* __restrict__ lin2_w,
                 const float* __restrict__ lin2_b,
                 float* __restrict__ out) {
    __shared__ float2 s_AC[Nn];
    __shared__ float4 s_P[Nn];
    __shared__ float4 s_Q[Nn];
    __shared__ float4 s_mom[2 * KMOM];
    __shared__ float  s_red[WARPS];
    __shared__ float  s_mean[3];
    __shared__ int    s_tk;

    const int b = blockIdx.y;
    const int tid = threadIdx.x;
    const int w = tid >> 5;
    const int lane = tid & 31;
    const int isB = g_isB;

    const int npj = g_npj[b];
    const int njc = (npj + 31) >> 5;
    const int jcap = min(Nn, (njc + 1) * 32);
    const int rb = blockIdx.x * ROWS_PER_BLOCK;

    if (tid < 2 * KMOM) s_mom[tid] = g_mom[b * 2 * KMOM + tid];

    if (rb < npj) {
        const float4* gp = (const float4*)&g_P[b * Nn];
        const float4* gq = (const float4*)&g_Q[b * Nn];
        const float4* ga = (const float4*)&g_AC[b * Nn];
        float4* sp = (float4*)s_P;
        float4* sq = (float4*)s_Q;
        float4* sa = (float4*)s_AC;
        for (int i = tid; i < jcap; i += THREADS) { sp[i] = gp[i]; sq[i] = gq[i]; }
        for (int i = tid; i < jcap / 2; i += THREADS) sa[i] = ga[i];
    }
    __syncthreads();

    const int p0 = rb + w * RPT;
    const float l2b = lin2_b[0];

    if (p0 < npj) {
        // ---- loop path ----
        const int cls0 = (p0 + RPT <= npj);

        u64c px2[NPAIR], py2[NPAIR], pz2[NPAIR], sq2[NPAIR], nrm2[NPAIR], rg2[NPAIR];
        u64c sum2[NPAIR], cx2[NPAIR], cy2[NPAIR], cz2[NPAIR];
        float nrmr[RPT];
        #pragma unroll
        for (int t = 0; t < NPAIR; t++) {
            int pa = p0 + 2 * t, pb_ = pa + 1;
            float4 Pa = s_P[pa], Pb = s_P[pb_];
            px2[t] = pk2(-0.5f * Pa.x, -0.5f * Pb.x);
            py2[t] = pk2(-0.5f * Pa.y, -0.5f * Pb.y);
            pz2[t] = pk2(-0.5f * Pa.z, -0.5f * Pb.z);
            sq2[t] = pk2(Pa.w, Pb.w);
            float4 Qa = s_Q[pa], Qb = s_Q[pb_];
            float na = sqrtf(fmaf(Qa.x, Qa.x, fmaf(Qa.y, Qa.y, Qa.z * Qa.z)));
            float nb = sqrtf(fmaf(Qb.x, Qb.x, fmaf(Qb.y, Qb.y, Qb.z * Qb.z)));
            nrmr[2 * t] = na; nrmr[2 * t + 1] = nb;
            nrm2[t] = pk2(na, nb);
            rg2[t] = pk2((pa < npj) ? 1.f : 0.f, (pb_ < npj) ? 1.f : 0.f);
            sum2[t] = 0ull; cx2[t] = 0ull; cy2[t] = 0ull; cz2[t] = 0ull;
        }

        if (cls0) {
            #pragma unroll 2
            for (int jj = 0; jj < njc; jj++) {
                const int j = jj * 32 + lane;
                const float2 AC = s_AC[j];
                const float4 P  = s_P[j];
                const float4 Q  = s_Q[j];
                u64c A2 = pk2(AC.x, AC.x), C2 = pk2(AC.y, AC.y);
                u64c Px2 = pk2(P.x, P.x), Py2 = pk2(P.y, P.y);
                u64c Pz2 = pk2(P.z, P.z), Pw2 = pk2(P.w, P.w);
                u64c Qx2 = pk2(Q.x, Q.x), Qy2 = pk2(Q.y, Q.y), Qz2 = pk2(Q.z, Q.z);
                u64c cb2 = pk2(Q.w, Q.w);
                #pragma unroll
                for (int t = 0; t < NPAIR; t++) {
                    u64c tt = fma2_(Pz2, pz2[t], Pw2);
                    tt = fma2_(Py2, py2[t], tt);
                    tt = fma2_(Px2, px2[t], tt);
                    u64c d2 = add2_(sq2[t], tt);
                    float da, db; upk2(da, db, d2);
                    float ra = sqrtf_(fmaxf(da, 1e-12f));
                    float rb_ = sqrtf_(fmaxf(db, 1e-12f));
                    u64c s2 = fma2_(nrm2[t], A2, C2);
                    s2 = fma2_(cb2, pk2(ra, rb_), s2);
                    float sa, sb; upk2(sa, sb, s2);
                    u64c e2 = pk2(ex2f_(sa), ex2f_(sb));
                    sum2[t] = add2_(sum2[t], e2);
                    cx2[t] = fma2_(e2, Qx2, cx2[t]);
                    cy2[t] = fma2_(e2, Qy2, cy2[t]);
                    cz2[t] = fma2_(e2, Qz2, cz2[t]);
                }
            }
        } else {
            #pragma unroll 2
            for (int jj = 0; jj < njc; jj++) {
                const int j = jj * 32 + lane;
                const float2 AC = s_AC[j];
                const float4 P  = s_P[j];
                const float4 Q  = s_Q[j];
                u64c A2 = pk2(AC.x, AC.x), C2 = pk2(AC.y, AC.y);
                u64c Px2 = pk2(P.x, P.x), Py2 = pk2(P.y, P.y);
                u64c Pz2 = pk2(P.z, P.z), Pw2 = pk2(P.w, P.w);
                u64c Qx2 = pk2(Q.x, Q.x), Qy2 = pk2(Q.y, Q.y), Qz2 = pk2(Q.z, Q.z);
                u64c cb2 = pk2(Q.w, Q.w);
                #pragma unroll
                for (int t = 0; t < NPAIR; t++) {
                    u64c tt = fma2_(Pz2, pz2[t], Pw2);
                    tt = fma2_(Py2, py2[t], tt);
                    tt = fma2_(Px2, px2[t], tt);
                    u64c d2 = add2_(sq2[t], tt);
                    float da, db; upk2(da, db, d2);
                    float ra = sqrtf_(fmaxf(da, 1e-12f));
                    float rb_ = sqrtf_(fmaxf(db, 1e-12f));
                    u64c cbt = mul2_(cb2, rg2[t]);
                    u64c s2 = fma2_(nrm2[t], A2, C2);
                    s2 = fma2_(cbt, pk2(ra, rb_), s2);
                    float sa, sb; upk2(sa, sb, s2);
                    u64c e2 = pk2(ex2f_(sa), ex2f_(sb));
                    sum2[t] = add2_(sum2[t], e2);
                    cx2[t] = fma2_(e2, Qx2, cx2[t]);
                    cy2[t] = fma2_(e2, Qy2, cy2[t]);
                    cz2[t] = fma2_(e2, Qz2, cz2[t]);
                }
            }
        }

        // warp-cooperative MLP for the 4 rows (h outer)
        float nnv[RPT];
        #pragma unroll
        for (int r = 0; r < RPT; r++) nnv[r] = 0.f;
        #pragma unroll
        for (int k = 0; k < Hh / 32; k++) {
            int h = k * 32 + lane;
            float w1 = __ldg(&lin1_w[h]), b1 = __ldg(&lin1_b[h]), w2 = __ldg(&lin2_w[h]);
            #pragma unroll
            for (int r = 0; r < RPT; r++)
                nnv[r] = fmaf(fmaxf(fmaf(nrmr[r], w1, b1), 0.f), w2, nnv[r]);
        }

        float sum[RPT], cx[RPT], cy[RPT], cz[RPT];
        #pragma unroll
        for (int t = 0; t < NPAIR; t++) {
            upk2(sum[2 * t], sum[2 * t + 1], sum2[t]);
            upk2(cx[2 * t],  cx[2 * t + 1],  cx2[t]);
            upk2(cy[2 * t],  cy[2 * t + 1],  cy2[t]);
            upk2(cz[2 * t],  cz[2 * t + 1],  cz2[t]);
        }
        #pragma unroll
        for (int r = 0; r < RPT; r++) {
            #pragma unroll
            for (int o = 16; o > 0; o >>= 1) {
                sum[r] += __shfl_xor_sync(0xFFFFFFFFu, sum[r], o);
                cx[r]  += __shfl_xor_sync(0xFFFFFFFFu, cx[r], o);
                cy[r]  += __shfl_xor_sync(0xFFFFFFFFu, cy[r], o);
                cz[r]  += __shfl_xor_sync(0xFFFFFFFFu, cz[r], o);
                nnv[r] += __shfl_xor_sync(0xFFFFFFFFu, nnv[r], o);
            }
        }

        #pragma unroll
        for (int r = 0; r < RPT; r++) {
            if (lane == r) {
                int pi = p0 + r;
                float4 Q = s_Q[pi];
                float4 P = s_P[pi];
                float nrm = nrmr[r];
                float S = sum[r], X = cx[r], Y = cy[r], Z = cz[r];
                float rgf = (pi < npj) ? 1.f : 0.f;
                float cbw = Q.w * rgf;
                float pxi = -0.5f * P.x, pyi = -0.5f * P.y, pzi = -0.5f * P.z;
                float e_wrong = pair_term(s_AC[pi], P, cbw, pxi, pyi, pzi, P.w, nrm);
                float e_right = ex2f_(fmaf(nrm, s_AC[pi].x, s_AC[pi].y));
                float d = e_right - e_wrong;
                S += d; X = fmaf(d, Q.x, X); Y = fmaf(d, Q.y, Y); Z = fmaf(d, Q.z, Z);
                float4 tc = mom_eval(&s_mom[KMOM], nrm - NU0);
                S += tc.x; X += tc.y; Y += tc.z; Z += tc.w;

                int oi = g_oidx[b * Nn + pi];
                int gi = b * Nn + oi;
                bool node = mask_at(node_mask, gi, isB);
                float f = node ? (nnv[r] + l2b) / (S * (nrm + 1e-5f)) : 0.f;
                out[gi * 3 + 0] = Q.x * X * f;
                out[gi * 3 + 1] = Q.y * Y * f;
                out[gi * 3 + 2] = Q.z * Z * f;
            }
        }
    } else {
        // ---- pure moment path ----
        float nrm_own = 0.f;
        float4 Qown;
        if (lane < RPT) {
            Qown = g_Q[b * Nn + p0 + lane];
            nrm_own = sqrtf(fmaf(Qown.x, Qown.x, fmaf(Qown.y, Qown.y, Qown.z * Qown.z)));
        }
        float nrmr[RPT];
        #pragma unroll
        for (int r = 0; r < RPT; r++)
            nrmr[r] = __shfl_sync(0xFFFFFFFFu, nrm_own, r);

        float nnv[RPT];
        #pragma unroll
        for (int r = 0; r < RPT; r++) nnv[r] = 0.f;
        #pragma unroll
        for (int k = 0; k < Hh / 32; k++) {
            int h = k * 32 + lane;
            float w1 = __ldg(&lin1_w[h]), b1 = __ldg(&lin1_b[h]), w2 = __ldg(&lin2_w[h]);
            #pragma unroll
            for (int r = 0; r < RPT; r++)
                nnv[r] = fmaf(fmaxf(fmaf(nrmr[r], w1, b1), 0.f), w2, nnv[r]);
        }
        #pragma unroll
        for (int r = 0; r < RPT; r++) {
            #pragma unroll
            for (int o = 16; o > 0; o >>= 1)
                nnv[r] += __shfl_xor_sync(0xFFFFFFFFu, nnv[r], o);
        }

        if (lane < RPT) {
            int pi = p0 + lane;
            float nrm = nrm_own;
            float dlt = nrm - NU0;
            float4 tp = mom_eval(&s_mom[0], dlt);
            float4 tc = mom_eval(&s_mom[KMOM], dlt);
            float S = tp.x + tc.x, X = tp.y + tc.y, Y = tp.z + tc.z, Z = tp.w + tc.w;
            int oi = g_oidx[b * Nn + pi];
            int gi = b * Nn + oi;
            bool node = mask_at(node_mask, gi, isB);
            float f = node ? (nnv[lane] + l2b) / (S * (nrm + 1e-5f)) : 0.f;
            out[gi * 3 + 0] = Qown.x * X * f;
            out[gi * 3 + 1] = Qown.y * Y * f;
            out[gi * 3 + 2] = Qown.z * Z * f;
        }
    }

    // fused per-batch mean subtraction (last block of batch)
    __threadfence();
    __syncthreads();
    if (tid == 0) s_tk = atomicAdd(&g_cnt[b], 1);
    __syncthreads();
    if (s_tk == GRIDX - 1) {
        __threadfence();
        float ax = 0.f, ay = 0.f, az = 0.f;
        for (int n = tid; n < Nn; n += THREADS) {
            const float* o = out + ((size_t)b * Nn + n) * 3;
            ax += o[0]; ay += o[1]; az += o[2];
        }
        float* comps[3] = {&ax, &ay, &az};
        #pragma unroll
        for (int c = 0; c < 3; c++) {
            float v = *comps[c];
            #pragma unroll
            for (int o = 16; o > 0; o >>= 1) v += __shfl_xor_sync(0xFFFFFFFFu, v, o);
            if (lane == 0) s_red[w] = v;
            __syncthreads();
            if (tid == 0) {
                float t = 0.f;
                #pragma unroll
                for (int k = 0; k < WARPS; k++) t += s_red[k];
                s_mean[c] = t * (1.f / Nn);
            }
            __syncthreads();
        }
        float mx = s_mean[0], my = s_mean[1], mz = s_mean[2];
        for (int n = tid; n < Nn; n += THREADS) {
            float* o = out + ((size_t)b * Nn + n) * 3;
            o[0] -= mx; o[1] -= my; o[2] -= mz;
        }
        if (tid == 0) atomicExch(&g_cnt[b], 0);
    }
}

extern "C" void kernel_launch(void* const* d_in, const int* in_sizes, int n_in,
                              void* d_out, int out_size) {
    const float* pos       = (const float*)d_in[0];
    const void*  node_mask = d_in[1];
    const float* p         = (const float*)d_in[2];
    const void*  pharma    = d_in[3];
    const float* lin1_w    = (const float*)d_in[4];
    const float* lin1_b    = (const float*)d_in[5];
    const float* lin2_w    = (const float*)d_in[6];
    const float* lin2_b    = (const float*)d_in[7];
    const float* wp        = (const float*)d_in[8];
    const float* bp        = (const float*)d_in[9];
    const float* wd        = (const float*)d_in[10];
    const float* wc        = (const float*)d_in[12];

    dim3 pgrid(Nn / THREADS, Bb);   // (4, 32)
    pre_kernel<<<pgrid, THREADS>>>(pos, node_mask, p, pharma,
                                   lin1_w, lin1_b, wp, bp, wd, wc);

    mom_kernel<<<Bb, 1024>>>();

    dim3 grid(GRIDX, Bb);
    attn_kernel<<<grid, THREADS>>>(node_mask, lin1_w, lin1_b, lin2_w, lin2_b,
                                   (float*)d_out);
}

// round 17
// speedup vs baseline: 1.2619x; 1.0122x over previous
#include <cuda_runtime.h>

#define Bb 32
#define Nn 1024
#define Hh 128
#define THREADS 256
#define WARPS 8
#define RPT 4
#define NPAIR 2
#define ROWS_PER_BLOCK (WARPS * RPT)  // 32
#define GRIDX (Nn / ROWS_PER_BLOCK)   // 32
#define KMOM 8
#define NU0 1.6f
#define LN2F 0.69314718056f

__device__ int   g_cnt[Bb];    // attn mean-sub tickets (reset after use)
__device__ int   g_cnt2[Bb];   // pre moment tickets (reset after use)
__device__ int   g_isB;        // mask dtype flag

// precomputed, pharma-first reordered per batch
__device__ float2 g_AC[Bb * Nn];
__device__ float4 g_P[Bb * Nn];
__device__ float4 g_Q[Bb * Nn];
__device__ int    g_oidx[Bb * Nn];
__device__ int    g_npj[Bb];

// per-batch cheap-sum moments: [b][seg][k] float4, seg0 = j<njc32, seg1 = rest
__device__ float4 g_mom[Bb * 2 * KMOM];

typedef unsigned long long u64c;

__device__ __forceinline__ float ex2f_(float x) {
    float y; asm("ex2.approx.ftz.f32 %0, %1;" : "=f"(y) : "f"(x)); return y;
}
__device__ __forceinline__ float sqrtf_(float x) {
    float y; asm("sqrt.approx.ftz.f32 %0, %1;" : "=f"(y) : "f"(x)); return y;
}
__device__ __forceinline__ bool mask_at(const void* m, int idx, int isByte) {
    if (isByte) return ((const unsigned char*)m)[idx] != 0;
    return ((const int*)m)[idx] != 0;
}

__device__ __forceinline__ u64c pk2(float lo, float hi) {
    u64c r; asm("mov.b64 %0, {%1, %2};" : "=l"(r) : "f"(lo), "f"(hi)); return r;
}
__device__ __forceinline__ void upk2(float& lo, float& hi, u64c v) {
    asm("mov.b64 {%0, %1}, %2;" : "=f"(lo), "=f"(hi) : "l"(v));
}
__device__ __forceinline__ u64c fma2_(u64c a, u64c b, u64c c) {
    u64c r; asm("fma.rn.f32x2 %0, %1, %2, %3;" : "=l"(r) : "l"(a), "l"(b), "l"(c)); return r;
}
__device__ __forceinline__ u64c add2_(u64c a, u64c b) {
    u64c r; asm("add.rn.f32x2 %0, %1, %2;" : "=l"(r) : "l"(a), "l"(b)); return r;
}
__device__ __forceinline__ u64c mul2_(u64c a, u64c b) {
    u64c r; asm("mul.rn.f32x2 %0, %1, %2;" : "=l"(r) : "l"(a), "l"(b)); return r;
}

__device__ __forceinline__ float pair_term(float2 AC, float4 P, float cbw,
                                           float pxi, float pyi, float pzi,
                                           float sqi, float nrm) {
    float t = fmaf(P.z, pzi, P.w);
    t = fmaf(P.y, pyi, t);
    t = fmaf(P.x, pxi, t);
    float d2 = fmaxf(sqi + t, 1e-12f);
    float dist = sqrtf_(d2);
    float s = fmaf(nrm, AC.x, AC.y);
    s = fmaf(cbw, dist, s);
    return ex2f_(s);
}

// Horner evaluation of the K-term moment polynomial at delta = nu - NU0.
__device__ __forceinline__ float4 mom_eval(const float4* __restrict__ m, float d) {
    float4 a = m[KMOM - 1];
    #pragma unroll
    for (int k = KMOM - 2; k >= 0; k--) {
        a.x = fmaf(a.x, d, m[k].x);
        a.y = fmaf(a.y, d, m[k].y);
        a.z = fmaf(a.z, d, m[k].z);
        a.w = fmaf(a.w, d, m[k].w);
    }
    return a;
}

// ---------------------------------------------------------------------------
// Precompute (grid (4,Bb) x 256): mask detect, 9-scalar collapse, pharma-first
// reorder + SoA. Last block per batch (ticket) also computes the moments.
// ---------------------------------------------------------------------------
__global__ __launch_bounds__(THREADS)
void pre_kernel(const float* __restrict__ pos,
                const void* __restrict__ node_mask,
                const float* __restrict__ p,
                const void* __restrict__ pharma,
                const float* __restrict__ lin1_w,
                const float* __restrict__ lin1_b,
                const float* __restrict__ wp,
                const float* __restrict__ bp,
                const float* __restrict__ wd,
                const float* __restrict__ wc) {
    __shared__ int    s_chk[32];
    __shared__ int    s_npj;
    __shared__ float  s_prm[9];
    __shared__ float4 s_part[WARPS][2 * KMOM];
    __shared__ int    s_tk;

    const int b = blockIdx.y;
    const int q = blockIdx.x;
    const int tid = threadIdx.x;
    const int w = tid >> 5;
    const int lane = tid & 31;

    // early, independent loads for pass 2 (overlap their latency with scan)
    const float* posb = pos + (size_t)b * Nn * 3;
    const float* pb   = p   + (size_t)b * Nn * 3;
    const int jme = q * THREADS + tid;
    float qx = posb[jme * 3 + 0], qy = posb[jme * 3 + 1], qz = posb[jme * 3 + 2];
    float px = pb[jme * 3 + 0],   py = pb[jme * 3 + 1],   pz = pb[jme * 3 + 2];

    int any = (tid < 256) && (((const unsigned int*)node_mask)[tid] > 1u);
    const int isB = __syncthreads_or(any) ? 1 : 0;

    if (w == 0) {
        const float L2E = 1.4426950408889634f;
        float u0 = 0.f, u1 = 0.f, u2 = 0.f, au = 0.f;
        float v0 = 0.f, v1 = 0.f, v2 = 0.f, av = 0.f, kd = 0.f;
        for (int h = lane; h < Hh; h += 32) {
            float w1h = wc[h];
            float w2h = wc[Hh + h];
            float a = lin1_w[h] * w1h;
            float c = lin1_b[h] * w1h;
            float wp0 = wp[h * 3 + 0], wp1 = wp[h * 3 + 1], wp2 = wp[h * 3 + 2];
            u0 = fmaf(a, wp0, u0); u1 = fmaf(a, wp1, u1); u2 = fmaf(a, wp2, u2);
            au = fmaf(a, bp[h], au);
            v0 = fmaf(c, wp0, v0); v1 = fmaf(c, wp1, v1); v2 = fmaf(c, wp2, v2);
            av = fmaf(c, bp[h], av);
            kd = fmaf(wd[h], w2h, kd);
        }
        #pragma unroll
        for (int o = 16; o > 0; o >>= 1) {
            u0 += __shfl_xor_sync(0xFFFFFFFFu, u0, o);
            u1 += __shfl_xor_sync(0xFFFFFFFFu, u1, o);
            u2 += __shfl_xor_sync(0xFFFFFFFFu, u2, o);
            au += __shfl_xor_sync(0xFFFFFFFFu, au, o);
            v0 += __shfl_xor_sync(0xFFFFFFFFu, v0, o);
            v1 += __shfl_xor_sync(0xFFFFFFFFu, v1, o);
            v2 += __shfl_xor_sync(0xFFFFFFFFu, v2, o);
            av += __shfl_xor_sync(0xFFFFFFFFu, av, o);
            kd += __shfl_xor_sync(0xFFFFFFFFu, kd, o);
        }
        if (lane == 0) {
            s_prm[0] = u0 * L2E; s_prm[1] = u1 * L2E; s_prm[2] = u2 * L2E; s_prm[3] = au * L2E;
            s_prm[4] = v0 * L2E; s_prm[5] = v1 * L2E; s_prm[6] = v2 * L2E; s_prm[7] = av * L2E;
            s_prm[8] = kd * L2E;
        }
    }

    #pragma unroll
    for (int k = 0; k < Nn / THREADS; k++) {
        int j = k * THREADS + tid;
        bool ph = mask_at(pharma, b * Nn + j, isB);
        unsigned m = __ballot_sync(0xFFFFFFFFu, ph);
        if (lane == 0) s_chk[k * WARPS + w] = __popc(m);
    }
    __syncthreads();
    if (tid < 32) {
        int v = s_chk[tid];
        int incl = v;
        #pragma unroll
        for (int o = 1; o < 32; o <<= 1) {
            int t = __shfl_up_sync(0xFFFFFFFFu, incl, o);
            if (lane >= o) incl += t;
        }
        s_chk[tid] = incl - v;
        if (tid == 31) s_npj = incl;
    }
    __syncthreads();
    const int npj = s_npj;

    const float u0 = s_prm[0], u1 = s_prm[1], u2 = s_prm[2], au = s_prm[3];
    const float v0 = s_prm[4], v1 = s_prm[5], v2 = s_prm[6], av = s_prm[7];
    const float kdL = s_prm[8];

    {
        bool ph = mask_at(pharma, b * Nn + jme, isB);
        unsigned m = __ballot_sync(0xFFFFFFFFu, ph);
        unsigned below = m & ((1u << lane) - 1u);
        int c = q * WARPS + w;
        int phOff = s_chk[c];
        int pos_;
        if (ph) pos_ = phOff + __popc(below);
        else    pos_ = npj + (c * 32 - phOff) + (lane - __popc(below));

        float A = fmaf(qx, u0, fmaf(qy, u1, fmaf(qz, u2, au)));
        float C = fmaf(qx, v0, fmaf(qy, v1, fmaf(qz, v2, av)));
        float sq = fmaf(px, px, fmaf(py, py, pz * pz));

        int gp = b * Nn + pos_;
        g_AC[gp] = make_float2(A, C);
        g_P[gp]  = make_float4(-2.f * px, -2.f * py, -2.f * pz, sq);
        g_Q[gp]  = make_float4(qx, qy, qz, ph ? kdL : 0.f);
        g_oidx[gp] = jme;
    }

    if (q == 0 && tid == 0) { g_npj[b] = npj; g_isB = isB; }

    // ---- fused moment phase: last of the 4 blocks per batch ----
    __threadfence();
    __syncthreads();
    if (tid == 0) s_tk = atomicAdd(&g_cnt2[b], 1);
    __syncthreads();
    if (s_tk == (Nn / THREADS) - 1) {
        __threadfence();
        const int njc32 = ((npj + 31) >> 5) << 5;

        float4 mp[KMOM], mc[KMOM];
        #pragma unroll
        for (int k = 0; k < KMOM; k++) {
            mp[k] = make_float4(0.f, 0.f, 0.f, 0.f);
            mc[k] = make_float4(0.f, 0.f, 0.f, 0.f);
        }
        #pragma unroll
        for (int rr = 0; rr < Nn / THREADS; rr++) {
            int j = rr * THREADS + tid;
            float2 ac = g_AC[b * Nn + j];
            float4 qv = g_Q[b * Nn + j];
            float e = ex2f_(fmaf(NU0, ac.x, ac.y));
            float t = ac.x * LN2F;
            bool isPh = (j < njc32);
            float wk = e;
            #pragma unroll
            for (int k = 0; k < KMOM; k++) {
                if (k > 0) wk *= t * (1.f / (float)k);
                float4 v = make_float4(wk, wk * qv.x, wk * qv.y, wk * qv.z);
                if (isPh) {
                    mp[k].x += v.x; mp[k].y += v.y; mp[k].z += v.z; mp[k].w += v.w;
                } else {
                    mc[k].x += v.x; mc[k].y += v.y; mc[k].z += v.z; mc[k].w += v.w;
                }
            }
        }
        // warp reduce
        #pragma unroll
        for (int k = 0; k < KMOM; k++) {
            #pragma unroll
            for (int o = 16; o > 0; o >>= 1) {
                mp[k].x += __shfl_xor_sync(0xFFFFFFFFu, mp[k].x, o);
                mp[k].y += __shfl_xor_sync(0xFFFFFFFFu, mp[k].y, o);
                mp[k].z += __shfl_xor_sync(0xFFFFFFFFu, mp[k].z, o);
                mp[k].w += __shfl_xor_sync(0xFFFFFFFFu, mp[k].w, o);
                mc[k].x += __shfl_xor_sync(0xFFFFFFFFu, mc[k].x, o);
                mc[k].y += __shfl_xor_sync(0xFFFFFFFFu, mc[k].y, o);
                mc[k].z += __shfl_xor_sync(0xFFFFFFFFu, mc[k].z, o);
                mc[k].w += __shfl_xor_sync(0xFFFFFFFFu, mc[k].w, o);
            }
        }
        if (lane == 0) {
            #pragma unroll
            for (int k = 0; k < KMOM; k++) {
                s_part[w][k] = mp[k];
                s_part[w][KMOM + k] = mc[k];
            }
        }
        __syncthreads();
        if (tid < 2 * KMOM) {
            float4 acc = make_float4(0.f, 0.f, 0.f, 0.f);
            #pragma unroll
            for (int k = 0; k < WARPS; k++) {
                float4 v = s_part[k][tid];
                acc.x += v.x; acc.y += v.y; acc.z += v.z; acc.w += v.w;
            }
            g_mom[b * 2 * KMOM + tid] = acc;
        }
        if (tid == 0) atomicExch(&g_cnt2[b], 0);   // reset for next replay
    }
}

// ---------------------------------------------------------------------------
// Main kernel: pharma rows = exact dist loop over j<njc32 + ch-moment poly;
// cheap rows = ph+ch moment polys. MLP computed warp-cooperatively here.
// ---------------------------------------------------------------------------
__global__ __launch_bounds__(THREADS, 3)
void attn_kernel(const void* __restrict__ node_mask,
                 const float* __restrict__ lin1_w,
                 const float* __restrict__ lin1_b,
                 const float* __restrict__ lin2_w,
                 const float* __restrict__ lin2_b,
                 float* __restrict__ out) {
    __shared__ float2 s_AC[Nn];
    __shared__ float4 s_P[Nn];
    __shared__ float4 s_Q[Nn];
    __shared__ float4 s_mom[2 * KMOM];
    __shared__ float  s_red[WARPS];
    __shared__ float  s_mean[3];
    __shared__ int    s_tk;

    const int b = blockIdx.y;
    const int tid = threadIdx.x;
    const int w = tid >> 5;
    const int lane = tid & 31;
    const int isB = g_isB;

    const int npj = g_npj[b];
    const int njc = (npj + 31) >> 5;
    const int jcap = min(Nn, (njc + 1) * 32);
    const int rb = blockIdx.x * ROWS_PER_BLOCK;

    if (tid < 2 * KMOM) s_mom[tid] = g_mom[b * 2 * KMOM + tid];

    if (rb < npj) {
        const float4* gp = (const float4*)&g_P[b * Nn];
        const float4* gq = (const float4*)&g_Q[b * Nn];
        const float4* ga = (const float4*)&g_AC[b * Nn];
        float4* sp = (float4*)s_P;
        float4* sq = (float4*)s_Q;
        float4* sa = (float4*)s_AC;
        for (int i = tid; i < jcap; i += THREADS) { sp[i] = gp[i]; sq[i] = gq[i]; }
        for (int i = tid; i < jcap / 2; i += THREADS) sa[i] = ga[i];
    }
    __syncthreads();

    const int p0 = rb + w * RPT;
    const float l2b = lin2_b[0];

    if (p0 < npj) {
        // ---- loop path ----
        const int cls0 = (p0 + RPT <= npj);

        u64c px2[NPAIR], py2[NPAIR], pz2[NPAIR], sq2[NPAIR], nrm2[NPAIR], rg2[NPAIR];
        u64c sum2[NPAIR], cx2[NPAIR], cy2[NPAIR], cz2[NPAIR];
        float nrmr[RPT];
        #pragma unroll
        for (int t = 0; t < NPAIR; t++) {
            int pa = p0 + 2 * t, pb_ = pa + 1;
            float4 Pa = s_P[pa], Pb = s_P[pb_];
            px2[t] = pk2(-0.5f * Pa.x, -0.5f * Pb.x);
            py2[t] = pk2(-0.5f * Pa.y, -0.5f * Pb.y);
            pz2[t] = pk2(-0.5f * Pa.z, -0.5f * Pb.z);
            sq2[t] = pk2(Pa.w, Pb.w);
            float4 Qa = s_Q[pa], Qb = s_Q[pb_];
            float na = sqrtf(fmaf(Qa.x, Qa.x, fmaf(Qa.y, Qa.y, Qa.z * Qa.z)));
            float nb = sqrtf(fmaf(Qb.x, Qb.x, fmaf(Qb.y, Qb.y, Qb.z * Qb.z)));
            nrmr[2 * t] = na; nrmr[2 * t + 1] = nb;
            nrm2[t] = pk2(na, nb);
            rg2[t] = pk2((pa < npj) ? 1.f : 0.f, (pb_ < npj) ? 1.f : 0.f);
            sum2[t] = 0ull; cx2[t] = 0ull; cy2[t] = 0ull; cz2[t] = 0ull;
        }

        if (cls0) {
            #pragma unroll 2
            for (int jj = 0; jj < njc; jj++) {
                const int j = jj * 32 + lane;
                const float2 AC = s_AC[j];
                const float4 P  = s_P[j];
                const float4 Q  = s_Q[j];
                u64c A2 = pk2(AC.x, AC.x), C2 = pk2(AC.y, AC.y);
                u64c Px2 = pk2(P.x, P.x), Py2 = pk2(P.y, P.y);
                u64c Pz2 = pk2(P.z, P.z), Pw2 = pk2(P.w, P.w);
                u64c Qx2 = pk2(Q.x, Q.x), Qy2 = pk2(Q.y, Q.y), Qz2 = pk2(Q.z, Q.z);
                u64c cb2 = pk2(Q.w, Q.w);
                #pragma unroll
                for (int t = 0; t < NPAIR; t++) {
                    u64c tt = fma2_(Pz2, pz2[t], Pw2);
                    tt = fma2_(Py2, py2[t], tt);
                    tt = fma2_(Px2, px2[t], tt);
                    u64c d2 = add2_(sq2[t], tt);
                    float da, db; upk2(da, db, d2);
                    float ra = sqrtf_(fmaxf(da, 1e-12f));
                    float rb_ = sqrtf_(fmaxf(db, 1e-12f));
                    u64c s2 = fma2_(nrm2[t], A2, C2);
                    s2 = fma2_(cb2, pk2(ra, rb_), s2);
                    float sa, sb; upk2(sa, sb, s2);
                    u64c e2 = pk2(ex2f_(sa), ex2f_(sb));
                    sum2[t] = add2_(sum2[t], e2);
                    cx2[t] = fma2_(e2, Qx2, cx2[t]);
                    cy2[t] = fma2_(e2, Qy2, cy2[t]);
                    cz2[t] = fma2_(e2, Qz2, cz2[t]);
                }
            }
        } else {
            #pragma unroll 2
            for (int jj = 0; jj < njc; jj++) {
                const int j = jj * 32 + lane;
                const float2 AC = s_AC[j];
                const float4 P  = s_P[j];
                const float4 Q  = s_Q[j];
                u64c A2 = pk2(AC.x, AC.x), C2 = pk2(AC.y, AC.y);
                u64c Px2 = pk2(P.x, P.x), Py2 = pk2(P.y, P.y);
                u64c Pz2 = pk2(P.z, P.z), Pw2 = pk2(P.w, P.w);
                u64c Qx2 = pk2(Q.x, Q.x), Qy2 = pk2(Q.y, Q.y), Qz2 = pk2(Q.z, Q.z);
                u64c cb2 = pk2(Q.w, Q.w);
                #pragma unroll
                for (int t = 0; t < NPAIR; t++) {
                    u64c tt = fma2_(Pz2, pz2[t], Pw2);
                    tt = fma2_(Py2, py2[t], tt);
                    tt = fma2_(Px2, px2[t], tt);
                    u64c d2 = add2_(sq2[t], tt);
                    float da, db; upk2(da, db, d2);
                    float ra = sqrtf_(fmaxf(da, 1e-12f));
                    float rb_ = sqrtf_(fmaxf(db, 1e-12f));
                    u64c cbt = mul2_(cb2, rg2[t]);
                    u64c s2 = fma2_(nrm2[t], A2, C2);
                    s2 = fma2_(cbt, pk2(ra, rb_), s2);
                    float sa, sb; upk2(sa, sb, s2);
                    u64c e2 = pk2(ex2f_(sa), ex2f_(sb));
                    sum2[t] = add2_(sum2[t], e2);
                    cx2[t] = fma2_(e2, Qx2, cx2[t]);
                    cy2[t] = fma2_(e2, Qy2, cy2[t]);
                    cz2[t] = fma2_(e2, Qz2, cz2[t]);
                }
            }
        }

        // warp-cooperative MLP for the 4 rows (h outer)
        float nnv[RPT];
        #pragma unroll
        for (int r = 0; r < RPT; r++) nnv[r] = 0.f;
        #pragma unroll
        for (int k = 0; k < Hh / 32; k++) {
            int h = k * 32 + lane;
            float w1 = __ldg(&lin1_w[h]), b1 = __ldg(&lin1_b[h]), w2 = __ldg(&lin2_w[h]);
            #pragma unroll
            for (int r = 0; r < RPT; r++)
                nnv[r] = fmaf(fmaxf(fmaf(nrmr[r], w1, b1), 0.f), w2, nnv[r]);
        }

        float sum[RPT], cx[RPT], cy[RPT], cz[RPT];
        #pragma unroll
        for (int t = 0; t < NPAIR; t++) {
            upk2(sum[2 * t], sum[2 * t + 1], sum2[t]);
            upk2(cx[2 * t],  cx[2 * t + 1],  cx2[t]);
            upk2(cy[2 * t],  cy[2 * t + 1],  cy2[t]);
            upk2(cz[2 * t],  cz[2 * t + 1],  cz2[t]);
        }
        #pragma unroll
        for (int r = 0; r < RPT; r++) {
            #pragma unroll
            for (int o = 16; o > 0; o >>= 1) {
                sum[r] += __shfl_xor_sync(0xFFFFFFFFu, sum[r], o);
                cx[r]  += __shfl_xor_sync(0xFFFFFFFFu, cx[r], o);
                cy[r]  += __shfl_xor_sync(0xFFFFFFFFu, cy[r], o);
                cz[r]  += __shfl_xor_sync(0xFFFFFFFFu, cz[r], o);
                nnv[r] += __shfl_xor_sync(0xFFFFFFFFu, nnv[r], o);
            }
        }

        #pragma unroll
        for (int r = 0; r < RPT; r++) {
            if (lane == r) {
                int pi = p0 + r;
                float4 Q = s_Q[pi];
                float4 P = s_P[pi];
                float nrm = nrmr[r];
                float S = sum[r], X = cx[r], Y = cy[r], Z = cz[r];
                float rgf = (pi < npj) ? 1.f : 0.f;
                float cbw = Q.w * rgf;
                float pxi = -0.5f * P.x, pyi = -0.5f * P.y, pzi = -0.5f * P.z;
                float e_wrong = pair_term(s_AC[pi], P, cbw, pxi, pyi, pzi, P.w, nrm);
                float e_right = ex2f_(fmaf(nrm, s_AC[pi].x, s_AC[pi].y));
                float d = e_right - e_wrong;
                S += d; X = fmaf(d, Q.x, X); Y = fmaf(d, Q.y, Y); Z = fmaf(d, Q.z, Z);
                float4 tc = mom_eval(&s_mom[KMOM], nrm - NU0);
                S += tc.x; X += tc.y; Y += tc.z; Z += tc.w;

                int oi = g_oidx[b * Nn + pi];
                int gi = b * Nn + oi;
                bool node = mask_at(node_mask, gi, isB);
                float f = node ? (nnv[r] + l2b) / (S * (nrm + 1e-5f)) : 0.f;
                out[gi * 3 + 0] = Q.x * X * f;
                out[gi * 3 + 1] = Q.y * Y * f;
                out[gi * 3 + 2] = Q.z * Z * f;
            }
        }
    } else {
        // ---- pure moment path ----
        float nrm_own = 0.f;
        float4 Qown;
        if (lane < RPT) {
            Qown = g_Q[b * Nn + p0 + lane];
            nrm_own = sqrtf(fmaf(Qown.x, Qown.x, fmaf(Qown.y, Qown.y, Qown.z * Qown.z)));
        }
        float nrmr[RPT];
        #pragma unroll
        for (int r = 0; r < RPT; r++)
            nrmr[r] = __shfl_sync(0xFFFFFFFFu, nrm_own, r);

        float nnv[RPT];
        #pragma unroll
        for (int r = 0; r < RPT; r++) nnv[r] = 0.f;
        #pragma unroll
        for (int k = 0; k < Hh / 32; k++) {
            int h = k * 32 + lane;
            float w1 = __ldg(&lin1_w[h]), b1 = __ldg(&lin1_b[h]), w2 = __ldg(&lin2_w[h]);
            #pragma unroll
            for (int r = 0; r < RPT; r++)
                nnv[r] = fmaf(fmaxf(fmaf(nrmr[r], w1, b1), 0.f), w2, nnv[r]);
        }
        #pragma unroll
        for (int r = 0; r < RPT; r++) {
            #pragma unroll
            for (int o = 16; o > 0; o >>= 1)
                nnv[r] += __shfl_xor_sync(0xFFFFFFFFu, nnv[r], o);
        }

        if (lane < RPT) {
            int pi = p0 + lane;
            float nrm = nrm_own;
            float dlt = nrm - NU0;
            float4 tp = mom_eval(&s_mom[0], dlt);
            float4 tc = mom_eval(&s_mom[KMOM], dlt);
            float S = tp.x + tc.x, X = tp.y + tc.y, Y = tp.z + tc.z, Z = tp.w + tc.w;
            int oi = g_oidx[b * Nn + pi];
            int gi = b * Nn + oi;
            bool node = mask_at(node_mask, gi, isB);
            float f = node ? (nnv[lane] + l2b) / (S * (nrm + 1e-5f)) : 0.f;
            out[gi * 3 + 0] = Qown.x * X * f;
            out[gi * 3 + 1] = Qown.y * Y * f;
            out[gi * 3 + 2] = Qown.z * Z * f;
        }
    }

    // fused per-batch mean subtraction (last block of batch)
    __threadfence();
    __syncthreads();
    if (tid == 0) s_tk = atomicAdd(&g_cnt[b], 1);
    __syncthreads();
    if (s_tk == GRIDX - 1) {
        __threadfence();
        float ax = 0.f, ay = 0.f, az = 0.f;
        for (int n = tid; n < Nn; n += THREADS) {
            const float* o = out + ((size_t)b * Nn + n) * 3;
            ax += o[0]; ay += o[1]; az += o[2];
        }
        float* comps[3] = {&ax, &ay, &az};
        #pragma unroll
        for (int c = 0; c < 3; c++) {
            float v = *comps[c];
            #pragma unroll
            for (int o = 16; o > 0; o >>= 1) v += __shfl_xor_sync(0xFFFFFFFFu, v, o);
            if (lane == 0) s_red[w] = v;
            __syncthreads();
            if (tid == 0) {
                float t = 0.f;
                #pragma unroll
                for (int k = 0; k < WARPS; k++) t += s_red[k];
                s_mean[c] = t * (1.f / Nn);
            }
            __syncthreads();
        }
        float mx = s_mean[0], my = s_mean[1], mz = s_mean[2];
        for (int n = tid; n < Nn; n += THREADS) {
            float* o = out + ((size_t)b * Nn + n) * 3;
            o[0] -= mx; o[1] -= my; o[2] -= mz;
        }
        if (tid == 0) atomicExch(&g_cnt[b], 0);
    }
}

extern "C" void kernel_launch(void* const* d_in, const int* in_sizes, int n_in,
                              void* d_out, int out_size) {
    const float* pos       = (const float*)d_in[0];
    const void*  node_mask = d_in[1];
    const float* p         = (const float*)d_in[2];
    const void*  pharma    = d_in[3];
    const float* lin1_w    = (const float*)d_in[4];
    const float* lin1_b    = (const float*)d_in[5];
    const float* lin2_w    = (const float*)d_in[6];
    const float* lin2_b    = (const float*)d_in[7];
    const float* wp        = (const float*)d_in[8];
    const float* bp        = (const float*)d_in[9];
    const float* wd        = (const float*)d_in[10];
    const float* wc        = (const float*)d_in[12];

    dim3 pgrid(Nn / THREADS, Bb);   // (4, 32)
    pre_kernel<<<pgrid, THREADS>>>(pos, node_mask, p, pharma,
                                   lin1_w, lin1_b, wp, bp, wd, wc);

    dim3 grid(GRIDX, Bb);
    attn_kernel<<<grid, THREADS>>>(node_mask, lin1_w, lin1_b, lin2_w, lin2_b,
                                   (float*)d_out);
}